// round 4
// baseline (speedup 1.0000x reference)
#include <cuda_runtime.h>

// Problem dims
#define NB  32
#define NT  512
#define ND  1024
#define NH  16
#define NHD 64
#define NM  (NB * NT)   // 16384 rows
#define N3D (3 * ND)    // 3072

// ---------------- scratch (allocation-free: __device__ globals) ----------------
__device__ float g_h[(size_t)NM * ND];        // 64 MB  : h = x@Wi + bi
__device__ float g_kqv[(size_t)NM * N3D];     // 192 MB : [K|Q|V] concat
__device__ float g_attn[(size_t)NM * ND];     // 64 MB  : attention out, [B,T,D]
__device__ float g_wpack[(size_t)ND * N3D];   // 12 MB  : packed [D, 3D] weight
__device__ float g_bpack[N3D];                // packed bias

// ---------------- pack Wk/Wq/Wv [H,D,HD] -> [D, 3D] row-major ----------------
__global__ void pack_kernel(const float* __restrict__ Wk, const float* __restrict__ Wq,
                            const float* __restrict__ Wv, const float* __restrict__ bk,
                            const float* __restrict__ bq, const float* __restrict__ bv) {
    int idx = blockIdx.x * blockDim.x + threadIdx.x;
    if (idx >= ND * N3D) return;
    int d = idx / N3D;
    int n = idx % N3D;
    int which = n / ND;         // 0:K 1:Q 2:V
    int nn = n % ND;            // h*HD + e
    int h = nn / NHD;
    int e = nn % NHD;
    const float* W = (which == 0) ? Wk : (which == 1) ? Wq : Wv;
    g_wpack[idx] = W[((size_t)h * ND + d) * NHD + e];
    if (d == 0) {
        const float* b = (which == 0) ? bk : (which == 1) ? bq : bv;
        g_bpack[n] = b[nn];     // bk flat layout [H,HD] == [nn]
    }
}

// ---------------- fp32 SGEMM: C[M,N] = A[M,K] @ B[K,N] + bias[N] ----------------
// BM=BN=128, BK=8, TM=TN=8, 256 threads. All dims are multiples of tiles.
template <int N, int K>
__global__ void __launch_bounds__(256)
sgemm_bias(const float* __restrict__ A, const float* __restrict__ B,
           const float* __restrict__ bias, float* __restrict__ C) {
    __shared__ float As[8][128];   // transposed A tile
    __shared__ float Bs[8][128];
    const int tid = threadIdx.x;
    const int cCol = blockIdx.x, cRow = blockIdx.y;
    A += (size_t)cRow * 128 * K;
    B += cCol * 128;
    C += (size_t)cRow * 128 * N + cCol * 128;
    const float* biasp = bias + cCol * 128;
    const int threadCol = tid % 16;
    const int threadRow = tid / 16;
    const int innerRowA = tid / 2;          // 0..127
    const int innerColA = (tid % 2) * 4;    // 0 or 4
    const int innerRowB = tid / 32;         // 0..7
    const int innerColB = (tid % 32) * 4;   // 0..124

    float acc[8][8];
#pragma unroll
    for (int i = 0; i < 8; i++)
#pragma unroll
        for (int j = 0; j < 8; j++) acc[i][j] = 0.f;

    for (int k0 = 0; k0 < K; k0 += 8) {
        float4 av = *(const float4*)(A + (size_t)innerRowA * K + k0 + innerColA);
        As[innerColA + 0][innerRowA] = av.x;
        As[innerColA + 1][innerRowA] = av.y;
        As[innerColA + 2][innerRowA] = av.z;
        As[innerColA + 3][innerRowA] = av.w;
        *(float4*)&Bs[innerRowB][innerColB] =
            *(const float4*)(B + (size_t)(k0 + innerRowB) * N + innerColB);
        __syncthreads();
#pragma unroll
        for (int kk = 0; kk < 8; kk++) {
            float4 m0 = *(const float4*)&As[kk][threadRow * 8];
            float4 m1 = *(const float4*)&As[kk][threadRow * 8 + 4];
            float4 n0 = *(const float4*)&Bs[kk][threadCol * 8];
            float4 n1 = *(const float4*)&Bs[kk][threadCol * 8 + 4];
            float rm[8] = {m0.x, m0.y, m0.z, m0.w, m1.x, m1.y, m1.z, m1.w};
            float rn[8] = {n0.x, n0.y, n0.z, n0.w, n1.x, n1.y, n1.z, n1.w};
#pragma unroll
            for (int i = 0; i < 8; i++)
#pragma unroll
                for (int j = 0; j < 8; j++)
                    acc[i][j] += rm[i] * rn[j];
        }
        __syncthreads();
    }
#pragma unroll
    for (int i = 0; i < 8; i++) {
        int row = threadRow * 8 + i;
#pragma unroll
        for (int j = 0; j < 8; j += 4) {
            int col = threadCol * 8 + j;
            float4 o;
            o.x = acc[i][j + 0] + biasp[col + 0];
            o.y = acc[i][j + 1] + biasp[col + 1];
            o.z = acc[i][j + 2] + biasp[col + 2];
            o.w = acc[i][j + 3] + biasp[col + 3];
            *(float4*)(C + (size_t)row * N + col) = o;
        }
    }
}

// ---------------- fused flash attention (k/q-swapped causal, fp32) ----------------
// wei[t,s] = k[t].q[s], mask s<=t, softmax over s, out[t] = sum_s p[t,s] v[s]
// One CTA per (tTile of 128 rows, head, batch). 256 threads, 16x16 grid, 8x8 S microtile.
#define SKST 65    // sK row stride  [128][65]
#define SQST 132   // sQt row stride [64][132]  (e-major, transposed Q)
#define SVST 68    // sV row stride  [128][68]
#define SPST 129   // sP row stride  [128][129]
#define ATTN_SMEM_BYTES ((128 * SKST + 64 * SQST + 128 * SVST + 128 * SPST) * 4)

__global__ void __launch_bounds__(256)
attn_kernel(const float* __restrict__ KQV, float* __restrict__ Out) {
    extern __shared__ float sm[];
    float* sK  = sm;                    // [128][SKST]
    float* sQt = sK + 128 * SKST;       // [64][SQST]
    float* sV  = sQt + 64 * SQST;       // [128][SVST]
    float* sP  = sV + 128 * SVST;       // [128][SPST]

    const int tTile = blockIdx.x;       // 0..3
    const int h = blockIdx.y;
    const int b = blockIdx.z;
    const int tid = threadIdx.x;
    const int tx = tid % 16, ty = tid / 16;
    const int r0 = ty * 8, c0 = tx * 8, cv0 = tx * 4;
    const int t0 = tTile * 128;

    const float* Kb = KQV + (size_t)b * NT * N3D + h * NHD;
    const float* Qb = Kb + ND;
    const float* Vb = Kb + 2 * ND;

    // load K tile (rows t0..t0+127, 64 cols), resident for whole CTA
    for (int i = tid; i < 128 * 64; i += 256) {
        int r = i >> 6, c = i & 63;
        sK[r * SKST + c] = Kb[(size_t)(t0 + r) * N3D + c];
    }

    float m_i[8], l_i[8], o[8][4];
#pragma unroll
    for (int i = 0; i < 8; i++) {
        m_i[i] = -1e30f; l_i[i] = 0.f;
#pragma unroll
        for (int c = 0; c < 4; c++) o[i][c] = 0.f;
    }

    for (int sTile = 0; sTile <= tTile; sTile++) {
        const int s0 = sTile * 128;
        __syncthreads();   // previous iteration done with sQt/sV/sP
        for (int i = tid; i < 128 * 64; i += 256) {
            int r = i >> 6, c = i & 63;
            sQt[c * SQST + r] = Qb[(size_t)(s0 + r) * N3D + c];  // transposed
            sV[r * SVST + c]  = Vb[(size_t)(s0 + r) * N3D + c];
        }
        __syncthreads();

        // S[r][c] = sum_e k[t0+r][e] * q[s0+c][e]
        float sacc[8][8];
#pragma unroll
        for (int i = 0; i < 8; i++)
#pragma unroll
            for (int j = 0; j < 8; j++) sacc[i][j] = 0.f;

        for (int e = 0; e < 64; e++) {
            float rk[8];
#pragma unroll
            for (int i = 0; i < 8; i++) rk[i] = sK[(r0 + i) * SKST + e];
            float4 q0 = *(const float4*)&sQt[e * SQST + c0];
            float4 q1 = *(const float4*)&sQt[e * SQST + c0 + 4];
            float rq[8] = {q0.x, q0.y, q0.z, q0.w, q1.x, q1.y, q1.z, q1.w};
#pragma unroll
            for (int i = 0; i < 8; i++)
#pragma unroll
                for (int j = 0; j < 8; j++)
                    sacc[i][j] += rk[i] * rq[j];
        }

        // causal mask: keep s <= t; only the diagonal tile is partial (s0 == t0)
        if (sTile == tTile) {
#pragma unroll
            for (int i = 0; i < 8; i++)
#pragma unroll
                for (int j = 0; j < 8; j++)
                    if (c0 + j > r0 + i) sacc[i][j] = -1e30f;
        }

        // online softmax per row; row stats reduced across the 16 lanes sharing ty
#pragma unroll
        for (int i = 0; i < 8; i++) {
            float mt = sacc[i][0];
#pragma unroll
            for (int j = 1; j < 8; j++) mt = fmaxf(mt, sacc[i][j]);
#pragma unroll
            for (int off = 1; off < 16; off <<= 1)
                mt = fmaxf(mt, __shfl_xor_sync(0xffffffffu, mt, off));
            float mnew = fmaxf(m_i[i], mt);
            float scale = __expf(m_i[i] - mnew);
            float ls = 0.f;
#pragma unroll
            for (int j = 0; j < 8; j++) {
                float p = __expf(sacc[i][j] - mnew);
                sacc[i][j] = p;
                ls += p;
            }
#pragma unroll
            for (int off = 1; off < 16; off <<= 1)
                ls += __shfl_xor_sync(0xffffffffu, ls, off);
            m_i[i] = mnew;
            l_i[i] = l_i[i] * scale + ls;
#pragma unroll
            for (int c = 0; c < 4; c++) o[i][c] *= scale;
#pragma unroll
            for (int j = 0; j < 8; j++)
                sP[(r0 + i) * SPST + c0 + j] = sacc[i][j];
        }
        __syncthreads();

        // O[r][c] += sum_s P[r][s] * V[s][c]; thread owns cols cv0..cv0+3
        for (int s = 0; s < 128; s++) {
            float4 rv = *(const float4*)&sV[s * SVST + cv0];
#pragma unroll
            for (int i = 0; i < 8; i++) {
                float p = sP[(r0 + i) * SPST + s];
                o[i][0] += p * rv.x;
                o[i][1] += p * rv.y;
                o[i][2] += p * rv.z;
                o[i][3] += p * rv.w;
            }
        }
    }

    // epilogue: normalize and scatter into [B,T,D] (head-concat layout)
#pragma unroll
    for (int i = 0; i < 8; i++) {
        float inv = 1.f / l_i[i];
        int t = t0 + r0 + i;
        float4 o4 = make_float4(o[i][0] * inv, o[i][1] * inv, o[i][2] * inv, o[i][3] * inv);
        *(float4*)(Out + ((size_t)b * NT + t) * ND + h * NHD + cv0) = o4;
    }
}

// ---------------- launch ----------------
extern "C" void kernel_launch(void* const* d_in, const int* in_sizes, int n_in,
                              void* d_out, int out_size) {
    const float* x  = (const float*)d_in[0];
    const float* Wi = (const float*)d_in[1];
    const float* bi = (const float*)d_in[2];
    const float* Wk = (const float*)d_in[3];
    const float* bk = (const float*)d_in[4];
    const float* Wq = (const float*)d_in[5];
    const float* bq = (const float*)d_in[6];
    const float* Wv = (const float*)d_in[7];
    const float* bv = (const float*)d_in[8];
    const float* Wo = (const float*)d_in[9];
    const float* bo = (const float*)d_in[10];
    float* out = (float*)d_out;

    float *ph, *pkqv, *pattn, *pwp, *pbp;
    cudaGetSymbolAddress((void**)&ph,    g_h);
    cudaGetSymbolAddress((void**)&pkqv,  g_kqv);
    cudaGetSymbolAddress((void**)&pattn, g_attn);
    cudaGetSymbolAddress((void**)&pwp,   g_wpack);
    cudaGetSymbolAddress((void**)&pbp,   g_bpack);

    cudaFuncSetAttribute(attn_kernel, cudaFuncAttributeMaxDynamicSharedMemorySize,
                         ATTN_SMEM_BYTES);

    // 1) pack per-head weights into [D, 3D]
    pack_kernel<<<(ND * N3D + 255) / 256, 256>>>(Wk, Wq, Wv, bk, bq, bv);

    // 2) h = x @ Wi + bi                      [16384,1024]
    sgemm_bias<ND, ND><<<dim3(ND / 128, NM / 128), 256>>>(x, Wi, bi, ph);

    // 3) [K|Q|V] = h @ Wpack + bpack          [16384,3072]
    sgemm_bias<N3D, ND><<<dim3(N3D / 128, NM / 128), 256>>>(ph, pwp, pbp, pkqv);

    // 4) fused causal flash attention -> g_attn in [B,T,D]
    attn_kernel<<<dim3(NT / 128, NH, NB), 256, ATTN_SMEM_BYTES>>>(pkqv, pattn);

    // 5) out = attn @ Wo + bo                 [16384,1024]
    sgemm_bias<ND, ND><<<dim3(ND / 128, NM / 128), 256>>>(pattn, Wo, bo, out);
}

// round 7
// speedup vs baseline: 1.6376x; 1.6376x over previous
#include <cuda_runtime.h>
#include <cuda_bf16.h>
#include <cstdint>

// Problem dims
#define NB  32
#define NT  512
#define ND  1024
#define NH  16
#define NHD 64
#define NM  (NB * NT)   // 16384 rows
#define N3D 3072
#define KCAT 3072       // tripled K for split-bf16 (hi|lo|hi) x (hi|hi|lo)
#define BK   32
#define NKIT (KCAT / BK)  // 96

// ---------------- scratch (allocation-free: __device__ globals) ----------------
__device__ float g_h[(size_t)NM * ND];                      // 64 MB
__device__ float g_kqv[(size_t)NM * N3D];                   // 192 MB
__device__ float g_attn[(size_t)NM * ND];                   // 64 MB
__device__ __nv_bfloat16 g_acat[(size_t)NM * KCAT];         // 96 MB  A concat (hi|lo|hi)
__device__ __nv_bfloat16 g_b1cat[(size_t)ND * KCAT];        // 6 MB   Wi^T concat
__device__ __nv_bfloat16 g_b2cat[(size_t)N3D * KCAT];       // 18 MB  Wkqv^T concat
__device__ __nv_bfloat16 g_b3cat[(size_t)ND * KCAT];        // 6 MB   Wo^T concat
__device__ float g_bpack[N3D];                              // packed kqv bias

// ---------------- PTX helpers (compute_103-safe: no tcgen05) ----------------
__device__ __forceinline__ uint32_t smem_u32(const void* p) {
    uint32_t a;
    asm("{ .reg .u64 t; cvta.to.shared.u64 t, %1; cvt.u32.u64 %0, t; }" : "=r"(a) : "l"(p));
    return a;
}
__device__ __forceinline__ void cp16(uint32_t dst, const void* src) {
    asm volatile("cp.async.cg.shared.global [%0], [%1], 16;" :: "r"(dst), "l"(src) : "memory");
}
#define LDSM_X4(r0, r1, r2, r3, addr) \
    asm volatile("ldmatrix.sync.aligned.m8n8.x4.shared.b16 {%0,%1,%2,%3}, [%4];" \
                 : "=r"(r0), "=r"(r1), "=r"(r2), "=r"(r3) : "r"(addr))
#define LDSM_X2(r0, r1, addr) \
    asm volatile("ldmatrix.sync.aligned.m8n8.x2.shared.b16 {%0,%1}, [%2];" \
                 : "=r"(r0), "=r"(r1) : "r"(addr))
__device__ __forceinline__ void mma16816(float* d, uint32_t a0, uint32_t a1, uint32_t a2,
                                         uint32_t a3, uint32_t b0, uint32_t b1) {
    asm volatile(
        "mma.sync.aligned.m16n8k16.row.col.f32.bf16.bf16.f32 "
        "{%0,%1,%2,%3}, {%4,%5,%6,%7}, {%8,%9}, {%0,%1,%2,%3};"
        : "+f"(d[0]), "+f"(d[1]), "+f"(d[2]), "+f"(d[3])
        : "r"(a0), "r"(a1), "r"(a2), "r"(a3), "r"(b0), "r"(b1));
}

// ---------------- conversion kernels (f32 -> split-bf16 concat, 16B vectorized) ----------------
// A: [M,1024] f32 -> [M,3072] bf16 blocks (hi | lo | hi). 8 elems per thread.
__global__ void convA_k(const float* __restrict__ X, __nv_bfloat16* __restrict__ O) {
    int idx = blockIdx.x * 256 + threadIdx.x;    // NM*128 threads
    int m = idx >> 7, kb = (idx & 127) * 8;
    const float* xp = X + (size_t)m * ND + kb;
    float v[8];
    *(float4*)&v[0] = *(const float4*)xp;
    *(float4*)&v[4] = *(const float4*)(xp + 4);
    __nv_bfloat16 hi[8], lo[8];
#pragma unroll
    for (int j = 0; j < 8; j++) {
        hi[j] = __float2bfloat16(v[j]);
        lo[j] = __float2bfloat16(v[j] - __bfloat162float(hi[j]));
    }
    __nv_bfloat16* r = O + (size_t)m * KCAT + kb;
    *(uint4*)(r)        = *(uint4*)hi;
    *(uint4*)(r + 1024) = *(uint4*)lo;
    *(uint4*)(r + 2048) = *(uint4*)hi;
}

// W: [K=1024, N=1024] f32 row-major -> [N,3072] bf16 (hi | hi | lo), coalesced writes
__global__ void convW_KN(const float* __restrict__ W, __nv_bfloat16* __restrict__ O) {
    int idx = blockIdx.x * 256 + threadIdx.x;    // 1024*128 threads
    int n = idx >> 7, kb = (idx & 127) * 8;
    __nv_bfloat16 hi[8], lo[8];
#pragma unroll
    for (int j = 0; j < 8; j++) {
        float v = W[(size_t)(kb + j) * ND + n];
        hi[j] = __float2bfloat16(v);
        lo[j] = __float2bfloat16(v - __bfloat162float(hi[j]));
    }
    __nv_bfloat16* r = O + (size_t)n * KCAT + kb;
    *(uint4*)(r)        = *(uint4*)hi;
    *(uint4*)(r + 1024) = *(uint4*)hi;
    *(uint4*)(r + 2048) = *(uint4*)lo;
}

// Wk/Wq/Wv [H,D,HD] -> [3072 n-rows, 3072] bf16 (hi|hi|lo) + packed bias
__global__ void convW_pack(const float* __restrict__ Wk, const float* __restrict__ Wq,
                           const float* __restrict__ Wv, const float* __restrict__ bk,
                           const float* __restrict__ bq, const float* __restrict__ bv,
                           __nv_bfloat16* __restrict__ O, float* __restrict__ bpack) {
    int idx = blockIdx.x * 256 + threadIdx.x;    // 3072*128 threads
    int n = idx >> 7, kb = (idx & 127) * 8;
    int which = n >> 10, nn = n & 1023, h = nn >> 6, e = nn & 63;
    const float* W = (which == 0) ? Wk : (which == 1) ? Wq : Wv;
    __nv_bfloat16 hi[8], lo[8];
#pragma unroll
    for (int j = 0; j < 8; j++) {
        float v = W[((size_t)h * ND + kb + j) * NHD + e];
        hi[j] = __float2bfloat16(v);
        lo[j] = __float2bfloat16(v - __bfloat162float(hi[j]));
    }
    __nv_bfloat16* r = O + (size_t)n * KCAT + kb;
    *(uint4*)(r)        = *(uint4*)hi;
    *(uint4*)(r + 1024) = *(uint4*)hi;
    *(uint4*)(r + 2048) = *(uint4*)lo;
    if (kb == 0) {
        const float* bb = (which == 0) ? bk : (which == 1) ? bq : bv;
        bpack[n] = bb[nn];
    }
}

// ---------------- HMMA bf16 GEMM: C[M,N] = Acat[M,3072] @ Bcat^T + bias ----------------
// 128x128 CTA tile, BK=32, 256 thr = 8 warps (2m x 4n), warp tile 64x32 of m16n8k16.
// 3-stage cp.async pipeline. Smem rows padded to 40 bf16 (conflict-free ldmatrix).
#define AST 40
#define TILE_BF16 (128 * AST)               // 5120 bf16 per tile
#define STG_BF16  (2 * TILE_BF16)           // A + B per stage
#define NSTAGE 3
#define GEMM_SMEM (NSTAGE * STG_BF16 * 2)   // 61440 bytes

template <int N>
__global__ void __launch_bounds__(256)
gemm_mma(const __nv_bfloat16* __restrict__ A, const __nv_bfloat16* __restrict__ Bt,
         const float* __restrict__ bias, float* __restrict__ C) {
    extern __shared__ __nv_bfloat16 sm[];
    const uint32_t sbase0 = smem_u32(sm);
    const int tid = threadIdx.x;
    const int bn = blockIdx.x, bm = blockIdx.y;
    const int lane = tid & 31, wid = tid >> 5;
    const int wm = wid & 1, wn = wid >> 1;

    // cp.async: each thread moves 2x16B for A and 2x16B for B per stage
    const int ldrow = tid >> 1;
    const int ldcol = (tid & 1) * 16;
    const __nv_bfloat16* Ag = A + (size_t)(bm * 128 + ldrow) * KCAT + ldcol;
    const __nv_bfloat16* Bg = Bt + (size_t)(bn * 128 + ldrow) * KCAT + ldcol;
    const uint32_t dOffA = (uint32_t)(ldrow * AST + ldcol) * 2;

    // ldmatrix lane address components
    const uint32_t aRowOff = (uint32_t)((wm * 64 + (lane & 15)) * AST + (lane >> 4) * 8) * 2;
    const uint32_t bRowOff = (uint32_t)((wn * 32 + (lane & 7)) * AST + ((lane >> 3) & 1) * 8) * 2;

    float acc[4][4][4];
#pragma unroll
    for (int mt = 0; mt < 4; mt++)
#pragma unroll
        for (int nt = 0; nt < 4; nt++)
#pragma unroll
            for (int r = 0; r < 4; r++) acc[mt][nt][r] = 0.f;

#pragma unroll
    for (int s = 0; s < NSTAGE - 1; s++) {
        uint32_t da = sbase0 + (uint32_t)s * STG_BF16 * 2 + dOffA;
        cp16(da, Ag + s * BK);
        cp16(da + 16, Ag + s * BK + 8);
        cp16(da + TILE_BF16 * 2, Bg + s * BK);
        cp16(da + TILE_BF16 * 2 + 16, Bg + s * BK + 8);
        asm volatile("cp.async.commit_group;" ::: "memory");
    }

    for (int kc = 0; kc < NKIT; kc++) {
        const int pf = kc + NSTAGE - 1;
        if (pf < NKIT) {
            uint32_t da = sbase0 + (uint32_t)(pf % NSTAGE) * STG_BF16 * 2 + dOffA;
            cp16(da, Ag + pf * BK);
            cp16(da + 16, Ag + pf * BK + 8);
            cp16(da + TILE_BF16 * 2, Bg + pf * BK);
            cp16(da + TILE_BF16 * 2 + 16, Bg + pf * BK + 8);
        }
        asm volatile("cp.async.commit_group;" ::: "memory");
        asm volatile("cp.async.wait_group 2;" ::: "memory");
        __syncthreads();

        const uint32_t sa = sbase0 + (uint32_t)(kc % NSTAGE) * STG_BF16 * 2;
        const uint32_t sb = sa + TILE_BF16 * 2;
#pragma unroll
        for (int ks = 0; ks < 2; ks++) {
            uint32_t af[4][4], bf[4][2];
#pragma unroll
            for (int mt = 0; mt < 4; mt++)
                LDSM_X4(af[mt][0], af[mt][1], af[mt][2], af[mt][3],
                        sa + aRowOff + (uint32_t)(mt * 16 * AST + ks * 16) * 2);
#pragma unroll
            for (int nt = 0; nt < 4; nt++)
                LDSM_X2(bf[nt][0], bf[nt][1],
                        sb + bRowOff + (uint32_t)(nt * 8 * AST + ks * 16) * 2);
#pragma unroll
            for (int mt = 0; mt < 4; mt++)
#pragma unroll
                for (int nt = 0; nt < 4; nt++)
                    mma16816(acc[mt][nt], af[mt][0], af[mt][1], af[mt][2], af[mt][3],
                             bf[nt][0], bf[nt][1]);
        }
        __syncthreads();
    }

    // epilogue: accum mapping m16n8 -> rows (lane/4, +8), cols 2*(lane%4)
#pragma unroll
    for (int mt = 0; mt < 4; mt++) {
        const int row = bm * 128 + wm * 64 + mt * 16 + (lane >> 2);
#pragma unroll
        for (int nt = 0; nt < 4; nt++) {
            const int col = bn * 128 + wn * 32 + nt * 8 + (lane & 3) * 2;
            const float2 b2 = *(const float2*)(bias + col);
            float2 o0 = make_float2(acc[mt][nt][0] + b2.x, acc[mt][nt][1] + b2.y);
            float2 o1 = make_float2(acc[mt][nt][2] + b2.x, acc[mt][nt][3] + b2.y);
            *(float2*)(C + (size_t)row * N + col) = o0;
            *(float2*)(C + (size_t)(row + 8) * N + col) = o1;
        }
    }
}

// ---------------- fused flash attention (unchanged fp32, k/q-swapped causal) ----------------
#define SKST 65
#define SQST 132
#define SVST 68
#define SPST 129
#define ATTN_SMEM_BYTES ((128 * SKST + 64 * SQST + 128 * SVST + 128 * SPST) * 4)

__global__ void __launch_bounds__(256)
attn_kernel(const float* __restrict__ KQV, float* __restrict__ Out) {
    extern __shared__ float smf[];
    float* sK  = smf;
    float* sQt = sK + 128 * SKST;
    float* sV  = sQt + 64 * SQST;
    float* sP  = sV + 128 * SVST;

    const int tTile = blockIdx.x;
    const int h = blockIdx.y;
    const int b = blockIdx.z;
    const int tid = threadIdx.x;
    const int tx = tid % 16, ty = tid / 16;
    const int r0 = ty * 8, c0 = tx * 8, cv0 = tx * 4;
    const int t0 = tTile * 128;

    const float* Kb = KQV + (size_t)b * NT * N3D + h * NHD;
    const float* Qb = Kb + ND;
    const float* Vb = Kb + 2 * ND;

    for (int i = tid; i < 128 * 64; i += 256) {
        int r = i >> 6, c = i & 63;
        sK[r * SKST + c] = Kb[(size_t)(t0 + r) * N3D + c];
    }

    float m_i[8], l_i[8], o[8][4];
#pragma unroll
    for (int i = 0; i < 8; i++) {
        m_i[i] = -1e30f; l_i[i] = 0.f;
#pragma unroll
        for (int c = 0; c < 4; c++) o[i][c] = 0.f;
    }

    for (int sTile = 0; sTile <= tTile; sTile++) {
        const int s0 = sTile * 128;
        __syncthreads();
        for (int i = tid; i < 128 * 64; i += 256) {
            int r = i >> 6, c = i & 63;
            sQt[c * SQST + r] = Qb[(size_t)(s0 + r) * N3D + c];
            sV[r * SVST + c]  = Vb[(size_t)(s0 + r) * N3D + c];
        }
        __syncthreads();

        float sacc[8][8];
#pragma unroll
        for (int i = 0; i < 8; i++)
#pragma unroll
            for (int j = 0; j < 8; j++) sacc[i][j] = 0.f;

        for (int e = 0; e < 64; e++) {
            float rk[8];
#pragma unroll
            for (int i = 0; i < 8; i++) rk[i] = sK[(r0 + i) * SKST + e];
            float4 q0 = *(const float4*)&sQt[e * SQST + c0];
            float4 q1 = *(const float4*)&sQt[e * SQST + c0 + 4];
            float rq[8] = {q0.x, q0.y, q0.z, q0.w, q1.x, q1.y, q1.z, q1.w};
#pragma unroll
            for (int i = 0; i < 8; i++)
#pragma unroll
                for (int j = 0; j < 8; j++)
                    sacc[i][j] += rk[i] * rq[j];
        }

        if (sTile == tTile) {
#pragma unroll
            for (int i = 0; i < 8; i++)
#pragma unroll
                for (int j = 0; j < 8; j++)
                    if (c0 + j > r0 + i) sacc[i][j] = -1e30f;
        }

#pragma unroll
        for (int i = 0; i < 8; i++) {
            float mt = sacc[i][0];
#pragma unroll
            for (int j = 1; j < 8; j++) mt = fmaxf(mt, sacc[i][j]);
#pragma unroll
            for (int off = 1; off < 16; off <<= 1)
                mt = fmaxf(mt, __shfl_xor_sync(0xffffffffu, mt, off));
            float mnew = fmaxf(m_i[i], mt);
            float scale = __expf(m_i[i] - mnew);
            float ls = 0.f;
#pragma unroll
            for (int j = 0; j < 8; j++) {
                float p = __expf(sacc[i][j] - mnew);
                sacc[i][j] = p;
                ls += p;
            }
#pragma unroll
            for (int off = 1; off < 16; off <<= 1)
                ls += __shfl_xor_sync(0xffffffffu, ls, off);
            m_i[i] = mnew;
            l_i[i] = l_i[i] * scale + ls;
#pragma unroll
            for (int c = 0; c < 4; c++) o[i][c] *= scale;
#pragma unroll
            for (int j = 0; j < 8; j++)
                sP[(r0 + i) * SPST + c0 + j] = sacc[i][j];
        }
        __syncthreads();

        for (int s = 0; s < 128; s++) {
            float4 rv = *(const float4*)&sV[s * SVST + cv0];
#pragma unroll
            for (int i = 0; i < 8; i++) {
                float p = sP[(r0 + i) * SPST + s];
                o[i][0] += p * rv.x;
                o[i][1] += p * rv.y;
                o[i][2] += p * rv.z;
                o[i][3] += p * rv.w;
            }
        }
    }

#pragma unroll
    for (int i = 0; i < 8; i++) {
        float inv = 1.f / l_i[i];
        int t = t0 + r0 + i;
        float4 o4 = make_float4(o[i][0] * inv, o[i][1] * inv, o[i][2] * inv, o[i][3] * inv);
        *(float4*)(Out + ((size_t)b * NT + t) * ND + h * NHD + cv0) = o4;
    }
}

// ---------------- launch ----------------
extern "C" void kernel_launch(void* const* d_in, const int* in_sizes, int n_in,
                              void* d_out, int out_size) {
    const float* x  = (const float*)d_in[0];
    const float* Wi = (const float*)d_in[1];
    const float* bi = (const float*)d_in[2];
    const float* Wk = (const float*)d_in[3];
    const float* bk = (const float*)d_in[4];
    const float* Wq = (const float*)d_in[5];
    const float* bq = (const float*)d_in[6];
    const float* Wv = (const float*)d_in[7];
    const float* bv = (const float*)d_in[8];
    const float* Wo = (const float*)d_in[9];
    const float* bo = (const float*)d_in[10];
    float* out = (float*)d_out;

    float *ph, *pkqv, *pattn, *pbp;
    __nv_bfloat16 *pacat, *pb1, *pb2, *pb3;
    cudaGetSymbolAddress((void**)&ph,    g_h);
    cudaGetSymbolAddress((void**)&pkqv,  g_kqv);
    cudaGetSymbolAddress((void**)&pattn, g_attn);
    cudaGetSymbolAddress((void**)&pbp,   g_bpack);
    cudaGetSymbolAddress((void**)&pacat, g_acat);
    cudaGetSymbolAddress((void**)&pb1,   g_b1cat);
    cudaGetSymbolAddress((void**)&pb2,   g_b2cat);
    cudaGetSymbolAddress((void**)&pb3,   g_b3cat);

    cudaFuncSetAttribute(attn_kernel, cudaFuncAttributeMaxDynamicSharedMemorySize,
                         ATTN_SMEM_BYTES);
    cudaFuncSetAttribute(gemm_mma<ND>,  cudaFuncAttributeMaxDynamicSharedMemorySize, GEMM_SMEM);
    cudaFuncSetAttribute(gemm_mma<N3D>, cudaFuncAttributeMaxDynamicSharedMemorySize, GEMM_SMEM);

    // weight conversions (hi|hi|lo concat, [N,3K] bf16 K-major)
    convW_pack<<<(N3D * 128) / 256, 256>>>(Wk, Wq, Wv, bk, bq, bv, pb2, pbp);
    convW_KN<<<(ND * 128) / 256, 256>>>(Wi, pb1);
    convW_KN<<<(ND * 128) / 256, 256>>>(Wo, pb3);

    // 1) h = x @ Wi + bi
    convA_k<<<(NM * 128) / 256, 256>>>(x, pacat);
    gemm_mma<ND><<<dim3(ND / 128, NM / 128), 256, GEMM_SMEM>>>(pacat, pb1, bi, ph);

    // 2) [K|Q|V] = h @ Wkqv + b
    convA_k<<<(NM * 128) / 256, 256>>>(ph, pacat);
    gemm_mma<N3D><<<dim3(N3D / 128, NM / 128), 256, GEMM_SMEM>>>(pacat, pb2, pbp, pkqv);

    // 3) fused causal flash attention
    attn_kernel<<<dim3(NT / 128, NH, NB), 256, ATTN_SMEM_BYTES>>>(pkqv, pattn);

    // 4) out = attn @ Wo + bo
    convA_k<<<(NM * 128) / 256, 256>>>(pattn, pacat);
    gemm_mma<ND><<<dim3(ND / 128, NM / 128), 256, GEMM_SMEM>>>(pacat, pb3, bo, out);
}

// round 12
// speedup vs baseline: 2.0590x; 1.2573x over previous
#include <cuda_runtime.h>
#include <cuda_bf16.h>
#include <cstdint>

// Problem dims
#define NB  32
#define NT  512
#define ND  1024
#define NH  16
#define NHD 64
#define NM  (NB * NT)   // 16384 rows
#define N3D 3072
#define KCAT 3072       // tripled K for split-bf16 (hi|lo|hi) x (hi|hi|lo)
#define BK   32
#define NKIT (KCAT / BK)  // 96

// ---------------- scratch (allocation-free: __device__ globals) ----------------
__device__ float g_kqv[(size_t)NM * N3D];                   // 192 MB
__device__ __nv_bfloat16 g_acat[(size_t)NM * KCAT];         // 96 MB  x-concat, later attn-concat
__device__ __nv_bfloat16 g_hcat[(size_t)NM * KCAT];         // 96 MB  h-concat
__device__ __nv_bfloat16 g_b1cat[(size_t)ND * KCAT];        // 6 MB   Wi^T concat
__device__ __nv_bfloat16 g_b2cat[(size_t)N3D * KCAT];       // 18 MB  Wkqv^T concat
__device__ __nv_bfloat16 g_b3cat[(size_t)ND * KCAT];        // 6 MB   Wo^T concat
__device__ float g_bpack[N3D];                              // packed kqv bias

// ---------------- PTX helpers (compute_103-safe) ----------------
__device__ __forceinline__ uint32_t smem_u32(const void* p) {
    uint32_t a;
    asm("{ .reg .u64 t; cvta.to.shared.u64 t, %1; cvt.u32.u64 %0, t; }" : "=r"(a) : "l"(p));
    return a;
}
__device__ __forceinline__ void cp16(uint32_t dst, const void* src) {
    asm volatile("cp.async.cg.shared.global [%0], [%1], 16;" :: "r"(dst), "l"(src) : "memory");
}
#define LDSM_X4(r0, r1, r2, r3, addr) \
    asm volatile("ldmatrix.sync.aligned.m8n8.x4.shared.b16 {%0,%1,%2,%3}, [%4];" \
                 : "=r"(r0), "=r"(r1), "=r"(r2), "=r"(r3) : "r"(addr))
__device__ __forceinline__ void mma16816(float* d, uint32_t a0, uint32_t a1, uint32_t a2,
                                         uint32_t a3, uint32_t b0, uint32_t b1) {
    asm volatile(
        "mma.sync.aligned.m16n8k16.row.col.f32.bf16.bf16.f32 "
        "{%0,%1,%2,%3}, {%4,%5,%6,%7}, {%8,%9}, {%0,%1,%2,%3};"
        : "+f"(d[0]), "+f"(d[1]), "+f"(d[2]), "+f"(d[3])
        : "r"(a0), "r"(a1), "r"(a2), "r"(a3), "r"(b0), "r"(b1));
}
__device__ __forceinline__ uint32_t pk2(float a, float b) {
    __nv_bfloat162 t = __floats2bfloat162_rn(a, b);
    return *(uint32_t*)&t;
}

// ---------------- conversion kernels ----------------
// A: [M,1024] f32 -> [M,3072] bf16 (hi | lo | hi)
__global__ void convA_k(const float* __restrict__ X, __nv_bfloat16* __restrict__ O) {
    int idx = blockIdx.x * 256 + threadIdx.x;    // NM*128 threads
    int m = idx >> 7, kb = (idx & 127) * 8;
    const float* xp = X + (size_t)m * ND + kb;
    float v[8];
    *(float4*)&v[0] = *(const float4*)xp;
    *(float4*)&v[4] = *(const float4*)(xp + 4);
    __nv_bfloat16 hi[8], lo[8];
#pragma unroll
    for (int j = 0; j < 8; j++) {
        hi[j] = __float2bfloat16(v[j]);
        lo[j] = __float2bfloat16(v[j] - __bfloat162float(hi[j]));
    }
    __nv_bfloat16* r = O + (size_t)m * KCAT + kb;
    *(uint4*)(r)        = *(uint4*)hi;
    *(uint4*)(r + 1024) = *(uint4*)lo;
    *(uint4*)(r + 2048) = *(uint4*)hi;
}

// W: [K=1024, N=1024] f32 row-major -> [N,3072] bf16 (hi | hi | lo)
__global__ void convW_KN(const float* __restrict__ W, __nv_bfloat16* __restrict__ O) {
    int idx = blockIdx.x * 256 + threadIdx.x;
    int n = idx >> 7, kb = (idx & 127) * 8;
    __nv_bfloat16 hi[8], lo[8];
#pragma unroll
    for (int j = 0; j < 8; j++) {
        float v = W[(size_t)(kb + j) * ND + n];
        hi[j] = __float2bfloat16(v);
        lo[j] = __float2bfloat16(v - __bfloat162float(hi[j]));
    }
    __nv_bfloat16* r = O + (size_t)n * KCAT + kb;
    *(uint4*)(r)        = *(uint4*)hi;
    *(uint4*)(r + 1024) = *(uint4*)hi;
    *(uint4*)(r + 2048) = *(uint4*)lo;
}

// Wk/Wq/Wv [H,D,HD] -> [3072 n-rows, 3072] bf16 (hi|hi|lo) + packed bias
__global__ void convW_pack(const float* __restrict__ Wk, const float* __restrict__ Wq,
                           const float* __restrict__ Wv, const float* __restrict__ bk,
                           const float* __restrict__ bq, const float* __restrict__ bv,
                           __nv_bfloat16* __restrict__ O, float* __restrict__ bpack) {
    int idx = blockIdx.x * 256 + threadIdx.x;
    int n = idx >> 7, kb = (idx & 127) * 8;
    int which = n >> 10, nn = n & 1023, h = nn >> 6, e = nn & 63;
    const float* W = (which == 0) ? Wk : (which == 1) ? Wq : Wv;
    __nv_bfloat16 hi[8], lo[8];
#pragma unroll
    for (int j = 0; j < 8; j++) {
        float v = W[((size_t)h * ND + kb + j) * NHD + e];
        hi[j] = __float2bfloat16(v);
        lo[j] = __float2bfloat16(v - __bfloat162float(hi[j]));
    }
    __nv_bfloat16* r = O + (size_t)n * KCAT + kb;
    *(uint4*)(r)        = *(uint4*)hi;
    *(uint4*)(r + 1024) = *(uint4*)hi;
    *(uint4*)(r + 2048) = *(uint4*)lo;
    if (kb == 0) {
        const float* bb = (which == 0) ? bk : (which == 1) ? bq : bv;
        bpack[n] = bb[nn];
    }
}

// ---------------- HMMA bf16 GEMM: C[M,N] = Acat[M,3072] @ Bcat^T + bias ----------------
// 128x128 CTA tile, BK=32, 128 thr = 4 warps (2m x 2n), warp tile 64x64.
// 4-stage cp.async pipeline. Smem rows padded to 40 bf16.
#define AST 40
#define TILE_B2 (128 * AST * 2)             // bytes per (A or B) tile: 10240
#define STG_B   (2 * TILE_B2)               // 20480 bytes per stage
#define NSTAGE 4
#define GEMM_SMEM (NSTAGE * STG_B)          // 81920 bytes

// CONCAT=0: f32 out, stride CN.  CONCAT=1: split-bf16 concat out, stride KCAT.
template <int CN, int CONCAT>
__global__ void __launch_bounds__(128)
gemm_mma(const __nv_bfloat16* __restrict__ A, const __nv_bfloat16* __restrict__ Bt,
         const float* __restrict__ bias, void* __restrict__ Cv) {
    extern __shared__ __nv_bfloat16 sm[];
    const uint32_t sbase0 = smem_u32(sm);
    const int tid = threadIdx.x;
    const int bn = blockIdx.x, bm = blockIdx.y;
    const int lane = tid & 31, wid = tid >> 5;
    const int wm = wid & 1, wn = wid >> 1;

    // cp.async addressing: thread handles rows (tid>>2)+32i, 16B chunk (tid&3)
    const int crow = tid >> 2;
    const int ccol = (tid & 3) * 8;
    const __nv_bfloat16* Ag = A + (size_t)(bm * 128 + crow) * KCAT + ccol;
    const __nv_bfloat16* Bg = Bt + (size_t)(bn * 128 + crow) * KCAT + ccol;
    const uint32_t dOff = (uint32_t)(crow * AST + ccol) * 2;

    // ldmatrix lane offsets
    const uint32_t aOff = (uint32_t)((wm * 64 + (lane & 15)) * AST + (lane >> 4) * 8) * 2;
    const uint32_t bOff = (uint32_t)((wn * 64 + (lane & 7) + ((lane >> 4) << 3)) * AST +
                                     ((lane >> 3) & 1) * 8) * 2;

    float acc[4][8][4];
#pragma unroll
    for (int mt = 0; mt < 4; mt++)
#pragma unroll
        for (int nt = 0; nt < 8; nt++)
#pragma unroll
            for (int r = 0; r < 4; r++) acc[mt][nt][r] = 0.f;

#pragma unroll
    for (int s = 0; s < NSTAGE - 1; s++) {
        uint32_t da = sbase0 + (uint32_t)s * STG_B + dOff;
#pragma unroll
        for (int i = 0; i < 4; i++) {
            cp16(da + (uint32_t)i * 32 * AST * 2, Ag + (size_t)i * 32 * KCAT + s * BK);
            cp16(da + TILE_B2 + (uint32_t)i * 32 * AST * 2, Bg + (size_t)i * 32 * KCAT + s * BK);
        }
        asm volatile("cp.async.commit_group;" ::: "memory");
    }

    for (int kc = 0; kc < NKIT; kc++) {
        const int pf = kc + NSTAGE - 1;
        if (pf < NKIT) {
            uint32_t da = sbase0 + (uint32_t)(pf % NSTAGE) * STG_B + dOff;
#pragma unroll
            for (int i = 0; i < 4; i++) {
                cp16(da + (uint32_t)i * 32 * AST * 2, Ag + (size_t)i * 32 * KCAT + pf * BK);
                cp16(da + TILE_B2 + (uint32_t)i * 32 * AST * 2,
                     Bg + (size_t)i * 32 * KCAT + pf * BK);
            }
        }
        asm volatile("cp.async.commit_group;" ::: "memory");
        asm volatile("cp.async.wait_group 3;" ::: "memory");
        __syncthreads();

        const uint32_t sa = sbase0 + (uint32_t)(kc % NSTAGE) * STG_B;
        const uint32_t sb = sa + TILE_B2;
#pragma unroll
        for (int ks = 0; ks < 2; ks++) {
            uint32_t af[4][4], bf[4][4];
#pragma unroll
            for (int mt = 0; mt < 4; mt++)
                LDSM_X4(af[mt][0], af[mt][1], af[mt][2], af[mt][3],
                        sa + aOff + (uint32_t)(mt * 16 * AST + ks * 16) * 2);
#pragma unroll
            for (int np = 0; np < 4; np++)
                LDSM_X4(bf[np][0], bf[np][1], bf[np][2], bf[np][3],
                        sb + bOff + (uint32_t)(np * 16 * AST + ks * 16) * 2);
#pragma unroll
            for (int mt = 0; mt < 4; mt++)
#pragma unroll
                for (int np = 0; np < 4; np++) {
                    mma16816(acc[mt][2 * np],     af[mt][0], af[mt][1], af[mt][2], af[mt][3],
                             bf[np][0], bf[np][1]);
                    mma16816(acc[mt][2 * np + 1], af[mt][0], af[mt][1], af[mt][2], af[mt][3],
                             bf[np][2], bf[np][3]);
                }
        }
        __syncthreads();
    }

    // epilogue
#pragma unroll
    for (int mt = 0; mt < 4; mt++) {
        const int row = bm * 128 + wm * 64 + mt * 16 + (lane >> 2);
#pragma unroll
        for (int nt = 0; nt < 8; nt++) {
            const int col = bn * 128 + wn * 64 + nt * 8 + (lane & 3) * 2;
            const float2 b2 = *(const float2*)(bias + col);
            float v0 = acc[mt][nt][0] + b2.x, v1 = acc[mt][nt][1] + b2.y;
            float v2 = acc[mt][nt][2] + b2.x, v3 = acc[mt][nt][3] + b2.y;
            if (CONCAT) {
                __nv_bfloat16* C = (__nv_bfloat16*)Cv;
                __nv_bfloat16 h0 = __float2bfloat16(v0), h1 = __float2bfloat16(v1);
                uint32_t hi01 = pk2(v0, v1);   // same rounding as __float2bfloat16
                uint32_t lo01 = pk2(v0 - __bfloat162float(h0), v1 - __bfloat162float(h1));
                __nv_bfloat16 h2 = __float2bfloat16(v2), h3 = __float2bfloat16(v3);
                uint32_t hi23 = pk2(v2, v3);
                uint32_t lo23 = pk2(v2 - __bfloat162float(h2), v3 - __bfloat162float(h3));
                size_t r0 = (size_t)row * KCAT, r1 = (size_t)(row + 8) * KCAT;
                *(uint32_t*)&C[r0 + col]        = hi01;
                *(uint32_t*)&C[r0 + 1024 + col] = lo01;
                *(uint32_t*)&C[r0 + 2048 + col] = hi01;
                *(uint32_t*)&C[r1 + col]        = hi23;
                *(uint32_t*)&C[r1 + 1024 + col] = lo23;
                *(uint32_t*)&C[r1 + 2048 + col] = hi23;
            } else {
                float* C = (float*)Cv;
                *(float2*)(C + (size_t)row * CN + col) = make_float2(v0, v1);
                *(float2*)(C + (size_t)(row + 8) * CN + col) = make_float2(v2, v3);
            }
        }
    }
}

// ---------------- HMMA flash attention (k/q-swapped causal, split-bf16 3-term) ----------------
// CTA = (tTile 128 rows, head, batch); 256 thr = 8 warps, warp owns 16 t-rows.
// S = K·Q^T via 3 passes (hi,hi),(lo,hi),(hi,lo); P kept in registers (C-frag -> A-frag
// repack); O += P·V via 3 passes with Vt[e][s_hi|s_lo] in smem.
#define KQST 136                             // [128][64hi|64lo] + pad
#define VTST 264                             // [64][128hi|128lo] + pad
#define ATTN_SMEM (2 * 128 * KQST * 2 + 64 * VTST * 2)   // 103424 B

__global__ void __launch_bounds__(256)
attn_mma(const float* __restrict__ KQV, __nv_bfloat16* __restrict__ Ocat) {
    extern __shared__ __nv_bfloat16 smb[];
    __nv_bfloat16* sK  = smb;
    __nv_bfloat16* sQ  = sK + 128 * KQST;
    __nv_bfloat16* sVt = sQ + 128 * KQST;
    const uint32_t sKa = smem_u32(sK), sQa = smem_u32(sQ), sVa = smem_u32(sVt);

    const int tTile = blockIdx.x, h = blockIdx.y, b = blockIdx.z;
    const int tid = threadIdx.x, lane = tid & 31, wid = tid >> 5;
    const int t0 = tTile * 128;

    const float* Kb = KQV + (size_t)b * NT * N3D + h * NHD;
    const float* Qb = Kb + ND;
    const float* Vb = Kb + 2 * ND;

    // K tile resident: [128][64hi|64lo]
    for (int i = tid; i < 2048; i += 256) {
        int row = i >> 4, q4 = (i & 15) * 4;
        float4 v = *(const float4*)(Kb + (size_t)(t0 + row) * N3D + q4);
        __nv_bfloat16 h0 = __float2bfloat16(v.x), h1 = __float2bfloat16(v.y);
        __nv_bfloat16 h2 = __float2bfloat16(v.z), h3 = __float2bfloat16(v.w);
        *(uint32_t*)&sK[row * KQST + q4]     = pk2(v.x, v.y);
        *(uint32_t*)&sK[row * KQST + q4 + 2] = pk2(v.z, v.w);
        *(uint32_t*)&sK[row * KQST + 64 + q4] =
            pk2(v.x - __bfloat162float(h0), v.y - __bfloat162float(h1));
        *(uint32_t*)&sK[row * KQST + 64 + q4 + 2] =
            pk2(v.z - __bfloat162float(h2), v.w - __bfloat162float(h3));
    }

    // ldmatrix lane offsets (element units, converted to bytes at use)
    const uint32_t aRow = (uint32_t)(wid * 16 + (lane & 15)) * KQST + (lane >> 4) * 8;
    const uint32_t bRowQ = (uint32_t)((lane & 7) + ((lane >> 4) << 3)) * KQST +
                           ((lane >> 3) & 1) * 8;
    const uint32_t bRowV = (uint32_t)((lane & 7) + ((lane >> 4) << 3)) * VTST +
                           ((lane >> 3) & 1) * 8;

    float oacc[8][4];
#pragma unroll
    for (int nt = 0; nt < 8; nt++)
#pragma unroll
        for (int r = 0; r < 4; r++) oacc[nt][r] = 0.f;
    float m0 = -1e30f, m1 = -1e30f, l0 = 0.f, l1 = 0.f;

    for (int sTile = 0; sTile <= tTile; sTile++) {
        const int s0 = sTile * 128;
        __syncthreads();
        // Q: [s][64hi|64lo]
        for (int i = tid; i < 2048; i += 256) {
            int row = i >> 4, q4 = (i & 15) * 4;
            float4 v = *(const float4*)(Qb + (size_t)(s0 + row) * N3D + q4);
            __nv_bfloat16 h0 = __float2bfloat16(v.x), h1 = __float2bfloat16(v.y);
            __nv_bfloat16 h2 = __float2bfloat16(v.z), h3 = __float2bfloat16(v.w);
            *(uint32_t*)&sQ[row * KQST + q4]     = pk2(v.x, v.y);
            *(uint32_t*)&sQ[row * KQST + q4 + 2] = pk2(v.z, v.w);
            *(uint32_t*)&sQ[row * KQST + 64 + q4] =
                pk2(v.x - __bfloat162float(h0), v.y - __bfloat162float(h1));
            *(uint32_t*)&sQ[row * KQST + 64 + q4 + 2] =
                pk2(v.z - __bfloat162float(h2), v.w - __bfloat162float(h3));
        }
        // V transposed: [e][s hi | s lo]
        for (int i = tid; i < 2048; i += 256) {
            int s = i >> 4, e4 = (i & 15) * 4;
            float4 v = *(const float4*)(Vb + (size_t)(s0 + s) * N3D + e4);
            float vv[4] = {v.x, v.y, v.z, v.w};
#pragma unroll
            for (int j = 0; j < 4; j++) {
                __nv_bfloat16 hh = __float2bfloat16(vv[j]);
                sVt[(e4 + j) * VTST + s] = hh;
                sVt[(e4 + j) * VTST + 128 + s] =
                    __float2bfloat16(vv[j] - __bfloat162float(hh));
            }
        }
        __syncthreads();

        // ---- S = K·Q^T (3 split passes) ----
        float sacc[16][4];
#pragma unroll
        for (int nt = 0; nt < 16; nt++)
#pragma unroll
            for (int r = 0; r < 4; r++) sacc[nt][r] = 0.f;

#pragma unroll
        for (int pass = 0; pass < 3; pass++) {
            const uint32_t ao = (pass == 1) ? 64u : 0u;
            const uint32_t bo = (pass == 2) ? 64u : 0u;
#pragma unroll
            for (int ks = 0; ks < 4; ks++) {
                uint32_t a0, a1, a2, a3;
                LDSM_X4(a0, a1, a2, a3, sKa + (aRow + ao + ks * 16) * 2);
#pragma unroll
                for (int np = 0; np < 8; np++) {
                    uint32_t b0, b1, b2, b3;
                    LDSM_X4(b0, b1, b2, b3,
                            sQa + (bRowQ + (uint32_t)np * 16 * KQST + bo + ks * 16) * 2);
                    mma16816(sacc[2 * np],     a0, a1, a2, a3, b0, b1);
                    mma16816(sacc[2 * np + 1], a0, a1, a2, a3, b2, b3);
                }
            }
        }

        // causal mask (diagonal tile only)
        if (sTile == tTile) {
            const int r0l = wid * 16 + (lane >> 2);
#pragma unroll
            for (int nt = 0; nt < 16; nt++) {
                const int c = nt * 8 + (lane & 3) * 2;
                if (c > r0l)         sacc[nt][0] = -1e30f;
                if (c + 1 > r0l)     sacc[nt][1] = -1e30f;
                if (c > r0l + 8)     sacc[nt][2] = -1e30f;
                if (c + 1 > r0l + 8) sacc[nt][3] = -1e30f;
            }
        }

        // ---- online softmax + register repack to P_hi/P_lo A-fragments ----
        float rm0 = -1e30f, rm1 = -1e30f;
#pragma unroll
        for (int nt = 0; nt < 16; nt++) {
            rm0 = fmaxf(rm0, fmaxf(sacc[nt][0], sacc[nt][1]));
            rm1 = fmaxf(rm1, fmaxf(sacc[nt][2], sacc[nt][3]));
        }
        rm0 = fmaxf(rm0, __shfl_xor_sync(0xffffffffu, rm0, 1));
        rm0 = fmaxf(rm0, __shfl_xor_sync(0xffffffffu, rm0, 2));
        rm1 = fmaxf(rm1, __shfl_xor_sync(0xffffffffu, rm1, 1));
        rm1 = fmaxf(rm1, __shfl_xor_sync(0xffffffffu, rm1, 2));
        const float mn0 = fmaxf(m0, rm0), mn1 = fmaxf(m1, rm1);
        const float sc0 = __expf(m0 - mn0), sc1 = __expf(m1 - mn1);

        uint32_t phi[8][4], plo[8][4];
        float ls0 = 0.f, ls1 = 0.f;
#pragma unroll
        for (int nt = 0; nt < 16; nt++) {
            float p0 = __expf(sacc[nt][0] - mn0);
            float p1 = __expf(sacc[nt][1] - mn0);
            float p2 = __expf(sacc[nt][2] - mn1);
            float p3 = __expf(sacc[nt][3] - mn1);
            ls0 += p0 + p1; ls1 += p2 + p3;
            __nv_bfloat16 h0 = __float2bfloat16(p0), h1 = __float2bfloat16(p1);
            __nv_bfloat16 h2 = __float2bfloat16(p2), h3 = __float2bfloat16(p3);
            const int j = nt >> 1, sl = (nt & 1) * 2;
            phi[j][sl]     = pk2(p0, p1);
            phi[j][sl + 1] = pk2(p2, p3);
            plo[j][sl]     = pk2(p0 - __bfloat162float(h0), p1 - __bfloat162float(h1));
            plo[j][sl + 1] = pk2(p2 - __bfloat162float(h2), p3 - __bfloat162float(h3));
        }
        ls0 += __shfl_xor_sync(0xffffffffu, ls0, 1);
        ls0 += __shfl_xor_sync(0xffffffffu, ls0, 2);
        ls1 += __shfl_xor_sync(0xffffffffu, ls1, 1);
        ls1 += __shfl_xor_sync(0xffffffffu, ls1, 2);
        l0 = l0 * sc0 + ls0;
        l1 = l1 * sc1 + ls1;
        m0 = mn0; m1 = mn1;
#pragma unroll
        for (int nt = 0; nt < 8; nt++) {
            oacc[nt][0] *= sc0; oacc[nt][1] *= sc0;
            oacc[nt][2] *= sc1; oacc[nt][3] *= sc1;
        }

        // ---- O += P·V (3 split passes: (hi,Vhi),(lo,Vhi),(hi,Vlo)) ----
#pragma unroll
        for (int pass = 0; pass < 3; pass++) {
            const uint32_t so = (pass == 2) ? 128u : 0u;
#pragma unroll
            for (int j = 0; j < 8; j++) {
                const uint32_t* pf = (pass == 1) ? plo[j] : phi[j];
#pragma unroll
                for (int np = 0; np < 4; np++) {   // FIX: 4 n-blocks (e=0..63), was 2
                    uint32_t b0, b1, b2, b3;
                    LDSM_X4(b0, b1, b2, b3,
                            sVa + (bRowV + (uint32_t)np * 16 * VTST + so + (uint32_t)j * 16) * 2);
                    mma16816(oacc[2 * np],     pf[0], pf[1], pf[2], pf[3], b0, b1);
                    mma16816(oacc[2 * np + 1], pf[0], pf[1], pf[2], pf[3], b2, b3);
                }
            }
        }
    }

    // epilogue: normalize, split to concat layout [m][hi|lo|hi]
    const float inv0 = 1.f / l0, inv1 = 1.f / l1;
    const int trow = t0 + wid * 16 + (lane >> 2);
    const size_t r0 = ((size_t)b * NT + trow) * KCAT;
    const size_t r1 = r0 + (size_t)8 * KCAT;
#pragma unroll
    for (int nt = 0; nt < 8; nt++) {
        const int col = h * NHD + nt * 8 + (lane & 3) * 2;
        float v0 = oacc[nt][0] * inv0, v1 = oacc[nt][1] * inv0;
        float v2 = oacc[nt][2] * inv1, v3 = oacc[nt][3] * inv1;
        __nv_bfloat16 h0 = __float2bfloat16(v0), h1 = __float2bfloat16(v1);
        __nv_bfloat16 h2 = __float2bfloat16(v2), h3 = __float2bfloat16(v3);
        uint32_t hi01 = pk2(v0, v1), hi23 = pk2(v2, v3);
        uint32_t lo01 = pk2(v0 - __bfloat162float(h0), v1 - __bfloat162float(h1));
        uint32_t lo23 = pk2(v2 - __bfloat162float(h2), v3 - __bfloat162float(h3));
        *(uint32_t*)&Ocat[r0 + col]        = hi01;
        *(uint32_t*)&Ocat[r0 + 1024 + col] = lo01;
        *(uint32_t*)&Ocat[r0 + 2048 + col] = hi01;
        *(uint32_t*)&Ocat[r1 + col]        = hi23;
        *(uint32_t*)&Ocat[r1 + 1024 + col] = lo23;
        *(uint32_t*)&Ocat[r1 + 2048 + col] = hi23;
    }
}

// ---------------- launch ----------------
extern "C" void kernel_launch(void* const* d_in, const int* in_sizes, int n_in,
                              void* d_out, int out_size) {
    const float* x  = (const float*)d_in[0];
    const float* Wi = (const float*)d_in[1];
    const float* bi = (const float*)d_in[2];
    const float* Wk = (const float*)d_in[3];
    const float* bk = (const float*)d_in[4];
    const float* Wq = (const float*)d_in[5];
    const float* bq = (const float*)d_in[6];
    const float* Wv = (const float*)d_in[7];
    const float* bv = (const float*)d_in[8];
    const float* Wo = (const float*)d_in[9];
    const float* bo = (const float*)d_in[10];
    float* out = (float*)d_out;

    float *pkqv, *pbp;
    __nv_bfloat16 *pacat, *phcat, *pb1, *pb2, *pb3;
    cudaGetSymbolAddress((void**)&pkqv,  g_kqv);
    cudaGetSymbolAddress((void**)&pbp,   g_bpack);
    cudaGetSymbolAddress((void**)&pacat, g_acat);
    cudaGetSymbolAddress((void**)&phcat, g_hcat);
    cudaGetSymbolAddress((void**)&pb1,   g_b1cat);
    cudaGetSymbolAddress((void**)&pb2,   g_b2cat);
    cudaGetSymbolAddress((void**)&pb3,   g_b3cat);

    cudaFuncSetAttribute(attn_mma, cudaFuncAttributeMaxDynamicSharedMemorySize, ATTN_SMEM);
    cudaFuncSetAttribute(gemm_mma<KCAT, 1>, cudaFuncAttributeMaxDynamicSharedMemorySize, GEMM_SMEM);
    cudaFuncSetAttribute(gemm_mma<N3D, 0>,  cudaFuncAttributeMaxDynamicSharedMemorySize, GEMM_SMEM);
    cudaFuncSetAttribute(gemm_mma<ND, 0>,   cudaFuncAttributeMaxDynamicSharedMemorySize, GEMM_SMEM);

    // weight conversions
    convW_pack<<<(N3D * 128) / 256, 256>>>(Wk, Wq, Wv, bk, bq, bv, pb2, pbp);
    convW_KN<<<(ND * 128) / 256, 256>>>(Wi, pb1);
    convW_KN<<<(ND * 128) / 256, 256>>>(Wo, pb3);

    // x -> concat
    convA_k<<<(NM * 128) / 256, 256>>>(x, pacat);

    // 1) h = x @ Wi + bi  (writes h directly in split-concat form)
    gemm_mma<KCAT, 1><<<dim3(ND / 128, NM / 128), 128, GEMM_SMEM>>>(pacat, pb1, bi, phcat);

    // 2) [K|Q|V] = h @ Wkqv + b  (f32)
    gemm_mma<N3D, 0><<<dim3(N3D / 128, NM / 128), 128, GEMM_SMEM>>>(phcat, pb2, pbp, pkqv);

    // 3) fused causal flash attention (writes attn out in split-concat form)
    attn_mma<<<dim3(NT / 128, NH, NB), 256, ATTN_SMEM>>>(pkqv, pacat);

    // 4) out = attn @ Wo + bo
    gemm_mma<ND, 0><<<dim3(ND / 128, NM / 128), 128, GEMM_SMEM>>>(pacat, pb3, bo, out);
}

// round 13
// speedup vs baseline: 2.1831x; 1.0603x over previous
#include <cuda_runtime.h>
#include <cuda_bf16.h>
#include <cstdint>

// Problem dims
#define NB  32
#define NT  512
#define ND  1024
#define NH  16
#define NHD 64
#define NM  (NB * NT)   // 16384 rows
#define N3D 3072
#define KCAT 3072       // tripled K for split-bf16 (hi|lo|hi) x (hi|hi|lo)
#define BK   32
#define NKIT (KCAT / BK)  // 96

// ---------------- scratch (allocation-free: __device__ globals) ----------------
__device__ float g_kqv[(size_t)NM * N3D];                   // 192 MB
__device__ __nv_bfloat16 g_acat[(size_t)NM * KCAT];         // 96 MB  x-concat, later attn-concat
__device__ __nv_bfloat16 g_hcat[(size_t)NM * KCAT];         // 96 MB  h-concat
__device__ __nv_bfloat16 g_b1cat[(size_t)ND * KCAT];        // 6 MB   Wi^T concat
__device__ __nv_bfloat16 g_b2cat[(size_t)N3D * KCAT];       // 18 MB  Wkqv^T concat
__device__ __nv_bfloat16 g_b3cat[(size_t)ND * KCAT];        // 6 MB   Wo^T concat
__device__ float g_bpack[N3D];                              // packed kqv bias

// ---------------- PTX helpers (compute_103-safe) ----------------
__device__ __forceinline__ uint32_t smem_u32(const void* p) {
    uint32_t a;
    asm("{ .reg .u64 t; cvta.to.shared.u64 t, %1; cvt.u32.u64 %0, t; }" : "=r"(a) : "l"(p));
    return a;
}
__device__ __forceinline__ void cp16(uint32_t dst, const void* src) {
    asm volatile("cp.async.cg.shared.global [%0], [%1], 16;" :: "r"(dst), "l"(src) : "memory");
}
#define LDSM_X4(r0, r1, r2, r3, addr) \
    asm volatile("ldmatrix.sync.aligned.m8n8.x4.shared.b16 {%0,%1,%2,%3}, [%4];" \
                 : "=r"(r0), "=r"(r1), "=r"(r2), "=r"(r3) : "r"(addr))
__device__ __forceinline__ void mma16816(float* d, uint32_t a0, uint32_t a1, uint32_t a2,
                                         uint32_t a3, uint32_t b0, uint32_t b1) {
    asm volatile(
        "mma.sync.aligned.m16n8k16.row.col.f32.bf16.bf16.f32 "
        "{%0,%1,%2,%3}, {%4,%5,%6,%7}, {%8,%9}, {%0,%1,%2,%3};"
        : "+f"(d[0]), "+f"(d[1]), "+f"(d[2]), "+f"(d[3])
        : "r"(a0), "r"(a1), "r"(a2), "r"(a3), "r"(b0), "r"(b1));
}
__device__ __forceinline__ uint32_t pk2(float a, float b) {
    __nv_bfloat162 t = __floats2bfloat162_rn(a, b);
    return *(uint32_t*)&t;
}

// ---------------- conversion kernels ----------------
// A: [M,1024] f32 -> [M,3072] bf16 (hi | lo | hi)
__global__ void convA_k(const float* __restrict__ X, __nv_bfloat16* __restrict__ O) {
    int idx = blockIdx.x * 256 + threadIdx.x;    // NM*128 threads
    int m = idx >> 7, kb = (idx & 127) * 8;
    const float* xp = X + (size_t)m * ND + kb;
    float v[8];
    *(float4*)&v[0] = *(const float4*)xp;
    *(float4*)&v[4] = *(const float4*)(xp + 4);
    __nv_bfloat16 hi[8], lo[8];
#pragma unroll
    for (int j = 0; j < 8; j++) {
        hi[j] = __float2bfloat16(v[j]);
        lo[j] = __float2bfloat16(v[j] - __bfloat162float(hi[j]));
    }
    __nv_bfloat16* r = O + (size_t)m * KCAT + kb;
    *(uint4*)(r)        = *(uint4*)hi;
    *(uint4*)(r + 1024) = *(uint4*)lo;
    *(uint4*)(r + 2048) = *(uint4*)hi;
}

// W: [K=1024, N=1024] f32 row-major -> [N,3072] bf16 (hi | hi | lo)
__global__ void convW_KN(const float* __restrict__ W, __nv_bfloat16* __restrict__ O) {
    int idx = blockIdx.x * 256 + threadIdx.x;
    int n = idx >> 7, kb = (idx & 127) * 8;
    __nv_bfloat16 hi[8], lo[8];
#pragma unroll
    for (int j = 0; j < 8; j++) {
        float v = W[(size_t)(kb + j) * ND + n];
        hi[j] = __float2bfloat16(v);
        lo[j] = __float2bfloat16(v - __bfloat162float(hi[j]));
    }
    __nv_bfloat16* r = O + (size_t)n * KCAT + kb;
    *(uint4*)(r)        = *(uint4*)hi;
    *(uint4*)(r + 1024) = *(uint4*)hi;
    *(uint4*)(r + 2048) = *(uint4*)lo;
}

// Wk/Wq/Wv [H,D,HD] -> [3072 n-rows, 3072] bf16 (hi|hi|lo) + packed bias
__global__ void convW_pack(const float* __restrict__ Wk, const float* __restrict__ Wq,
                           const float* __restrict__ Wv, const float* __restrict__ bk,
                           const float* __restrict__ bq, const float* __restrict__ bv,
                           __nv_bfloat16* __restrict__ O, float* __restrict__ bpack) {
    int idx = blockIdx.x * 256 + threadIdx.x;
    int n = idx >> 7, kb = (idx & 127) * 8;
    int which = n >> 10, nn = n & 1023, h = nn >> 6, e = nn & 63;
    const float* W = (which == 0) ? Wk : (which == 1) ? Wq : Wv;
    __nv_bfloat16 hi[8], lo[8];
#pragma unroll
    for (int j = 0; j < 8; j++) {
        float v = W[((size_t)h * ND + kb + j) * NHD + e];
        hi[j] = __float2bfloat16(v);
        lo[j] = __float2bfloat16(v - __bfloat162float(hi[j]));
    }
    __nv_bfloat16* r = O + (size_t)n * KCAT + kb;
    *(uint4*)(r)        = *(uint4*)hi;
    *(uint4*)(r + 1024) = *(uint4*)hi;
    *(uint4*)(r + 2048) = *(uint4*)lo;
    if (kb == 0) {
        const float* bb = (which == 0) ? bk : (which == 1) ? bq : bv;
        bpack[n] = bb[nn];
    }
}

// ---------------- HMMA bf16 GEMM: C[M,N] = Acat[M,3072] @ Bcat^T + bias ----------------
// 128x128 CTA tile, BK=32, 128 thr = 4 warps (2m x 2n), warp tile 64x64.
// 5-stage cp.async pipeline, SINGLE barrier per k-chunk (CUTLASS multistage shape).
#define AST 40
#define TILE_B2 (128 * AST * 2)             // bytes per (A or B) tile: 10240
#define STG_B   (2 * TILE_B2)               // 20480 bytes per stage
#define NSTAGE 5
#define GEMM_SMEM (NSTAGE * STG_B)          // 102400 bytes

// CONCAT=0: f32 out, stride CN.  CONCAT=1: split-bf16 concat out, stride KCAT.
template <int CN, int CONCAT>
__global__ void __launch_bounds__(128)
gemm_mma(const __nv_bfloat16* __restrict__ A, const __nv_bfloat16* __restrict__ Bt,
         const float* __restrict__ bias, void* __restrict__ Cv) {
    extern __shared__ __nv_bfloat16 sm[];
    const uint32_t sbase0 = smem_u32(sm);
    const int tid = threadIdx.x;
    const int bn = blockIdx.x, bm = blockIdx.y;
    const int lane = tid & 31, wid = tid >> 5;
    const int wm = wid & 1, wn = wid >> 1;

    // cp.async addressing: thread handles rows (tid>>2)+32i, 16B chunk (tid&3)
    const int crow = tid >> 2;
    const int ccol = (tid & 3) * 8;
    const __nv_bfloat16* Ag = A + (size_t)(bm * 128 + crow) * KCAT + ccol;
    const __nv_bfloat16* Bg = Bt + (size_t)(bn * 128 + crow) * KCAT + ccol;
    const uint32_t dOff = (uint32_t)(crow * AST + ccol) * 2;

    // ldmatrix lane offsets
    const uint32_t aOff = (uint32_t)((wm * 64 + (lane & 15)) * AST + (lane >> 4) * 8) * 2;
    const uint32_t bOff = (uint32_t)((wn * 64 + (lane & 7) + ((lane >> 4) << 3)) * AST +
                                     ((lane >> 3) & 1) * 8) * 2;

    float acc[4][8][4];
#pragma unroll
    for (int mt = 0; mt < 4; mt++)
#pragma unroll
        for (int nt = 0; nt < 8; nt++)
#pragma unroll
            for (int r = 0; r < 4; r++) acc[mt][nt][r] = 0.f;

#pragma unroll
    for (int s = 0; s < NSTAGE - 1; s++) {
        uint32_t da = sbase0 + (uint32_t)s * STG_B + dOff;
#pragma unroll
        for (int i = 0; i < 4; i++) {
            cp16(da + (uint32_t)i * 32 * AST * 2, Ag + (size_t)i * 32 * KCAT + s * BK);
            cp16(da + TILE_B2 + (uint32_t)i * 32 * AST * 2, Bg + (size_t)i * 32 * KCAT + s * BK);
        }
        asm volatile("cp.async.commit_group;" ::: "memory");
    }

    int rb = 0, wb = NSTAGE - 1;
    for (int kc = 0; kc < NKIT; kc++) {
        // stage rb (data for chunk kc) ready when <= NSTAGE-2 groups outstanding
        asm volatile("cp.async.wait_group 3;" ::: "memory");
        __syncthreads();   // all warps done with buffer wb (read NSTAGE-1 chunks ago)

        const int pf = kc + NSTAGE - 1;
        if (pf < NKIT) {
            uint32_t da = sbase0 + (uint32_t)wb * STG_B + dOff;
#pragma unroll
            for (int i = 0; i < 4; i++) {
                cp16(da + (uint32_t)i * 32 * AST * 2, Ag + (size_t)i * 32 * KCAT + pf * BK);
                cp16(da + TILE_B2 + (uint32_t)i * 32 * AST * 2,
                     Bg + (size_t)i * 32 * KCAT + pf * BK);
            }
        }
        asm volatile("cp.async.commit_group;" ::: "memory");

        const uint32_t sa = sbase0 + (uint32_t)rb * STG_B;
        const uint32_t sb = sa + TILE_B2;
#pragma unroll
        for (int ks = 0; ks < 2; ks++) {
            uint32_t af[4][4], bf[4][4];
#pragma unroll
            for (int mt = 0; mt < 4; mt++)
                LDSM_X4(af[mt][0], af[mt][1], af[mt][2], af[mt][3],
                        sa + aOff + (uint32_t)(mt * 16 * AST + ks * 16) * 2);
#pragma unroll
            for (int np = 0; np < 4; np++)
                LDSM_X4(bf[np][0], bf[np][1], bf[np][2], bf[np][3],
                        sb + bOff + (uint32_t)(np * 16 * AST + ks * 16) * 2);
#pragma unroll
            for (int mt = 0; mt < 4; mt++)
#pragma unroll
                for (int np = 0; np < 4; np++) {
                    mma16816(acc[mt][2 * np],     af[mt][0], af[mt][1], af[mt][2], af[mt][3],
                             bf[np][0], bf[np][1]);
                    mma16816(acc[mt][2 * np + 1], af[mt][0], af[mt][1], af[mt][2], af[mt][3],
                             bf[np][2], bf[np][3]);
                }
        }
        rb = (rb + 1 == NSTAGE) ? 0 : rb + 1;
        wb = (wb + 1 == NSTAGE) ? 0 : wb + 1;
    }

    // epilogue
#pragma unroll
    for (int mt = 0; mt < 4; mt++) {
        const int row = bm * 128 + wm * 64 + mt * 16 + (lane >> 2);
#pragma unroll
        for (int nt = 0; nt < 8; nt++) {
            const int col = bn * 128 + wn * 64 + nt * 8 + (lane & 3) * 2;
            const float2 b2 = *(const float2*)(bias + col);
            float v0 = acc[mt][nt][0] + b2.x, v1 = acc[mt][nt][1] + b2.y;
            float v2 = acc[mt][nt][2] + b2.x, v3 = acc[mt][nt][3] + b2.y;
            if (CONCAT) {
                __nv_bfloat16* C = (__nv_bfloat16*)Cv;
                __nv_bfloat16 h0 = __float2bfloat16(v0), h1 = __float2bfloat16(v1);
                uint32_t hi01 = pk2(v0, v1);
                uint32_t lo01 = pk2(v0 - __bfloat162float(h0), v1 - __bfloat162float(h1));
                __nv_bfloat16 h2 = __float2bfloat16(v2), h3 = __float2bfloat16(v3);
                uint32_t hi23 = pk2(v2, v3);
                uint32_t lo23 = pk2(v2 - __bfloat162float(h2), v3 - __bfloat162float(h3));
                size_t r0 = (size_t)row * KCAT, r1 = (size_t)(row + 8) * KCAT;
                *(uint32_t*)&C[r0 + col]        = hi01;
                *(uint32_t*)&C[r0 + 1024 + col] = lo01;
                *(uint32_t*)&C[r0 + 2048 + col] = hi01;
                *(uint32_t*)&C[r1 + col]        = hi23;
                *(uint32_t*)&C[r1 + 1024 + col] = lo23;
                *(uint32_t*)&C[r1 + 2048 + col] = hi23;
            } else {
                float* C = (float*)Cv;
                *(float2*)(C + (size_t)row * CN + col) = make_float2(v0, v1);
                *(float2*)(C + (size_t)(row + 8) * CN + col) = make_float2(v2, v3);
            }
        }
    }
}

// ---------------- HMMA flash attention (k/q-swapped causal, split-bf16 3-term) ----------------
// CTA = (tTile 128 rows, head, batch); 256 thr = 8 warps, warp owns 16 t-rows.
// K fragments hoisted to registers; split passes sharing a B fragment are fused;
// fully-masked diagonal blocks are skipped.
#define KQST 136                             // [128][64hi|64lo] + pad
#define VTST 264                             // [64][128hi|128lo] + pad
#define ATTN_SMEM (2 * 128 * KQST * 2 + 64 * VTST * 2)   // 103424 B

__global__ void __launch_bounds__(256)
attn_mma(const float* __restrict__ KQV, __nv_bfloat16* __restrict__ Ocat) {
    extern __shared__ __nv_bfloat16 smb[];
    __nv_bfloat16* sK  = smb;
    __nv_bfloat16* sQ  = sK + 128 * KQST;
    __nv_bfloat16* sVt = sQ + 128 * KQST;
    const uint32_t sKa = smem_u32(sK), sQa = smem_u32(sQ), sVa = smem_u32(sVt);

    const int tTile = blockIdx.x, h = blockIdx.y, b = blockIdx.z;
    const int tid = threadIdx.x, lane = tid & 31, wid = tid >> 5;
    const int t0 = tTile * 128;

    const float* Kb = KQV + (size_t)b * NT * N3D + h * NHD;
    const float* Qb = Kb + ND;
    const float* Vb = Kb + 2 * ND;

    // K tile resident: [128][64hi|64lo]
    for (int i = tid; i < 2048; i += 256) {
        int row = i >> 4, q4 = (i & 15) * 4;
        float4 v = *(const float4*)(Kb + (size_t)(t0 + row) * N3D + q4);
        __nv_bfloat16 h0 = __float2bfloat16(v.x), h1 = __float2bfloat16(v.y);
        __nv_bfloat16 h2 = __float2bfloat16(v.z), h3 = __float2bfloat16(v.w);
        *(uint32_t*)&sK[row * KQST + q4]     = pk2(v.x, v.y);
        *(uint32_t*)&sK[row * KQST + q4 + 2] = pk2(v.z, v.w);
        *(uint32_t*)&sK[row * KQST + 64 + q4] =
            pk2(v.x - __bfloat162float(h0), v.y - __bfloat162float(h1));
        *(uint32_t*)&sK[row * KQST + 64 + q4 + 2] =
            pk2(v.z - __bfloat162float(h2), v.w - __bfloat162float(h3));
    }
    __syncthreads();

    // ldmatrix lane offsets (element units, bytes at use)
    const uint32_t aRow = (uint32_t)(wid * 16 + (lane & 15)) * KQST + (lane >> 4) * 8;
    const uint32_t bRowQ = (uint32_t)((lane & 7) + ((lane >> 4) << 3)) * KQST +
                           ((lane >> 3) & 1) * 8;
    const uint32_t bRowV = (uint32_t)((lane & 7) + ((lane >> 4) << 3)) * VTST +
                           ((lane >> 3) & 1) * 8;

    // hoist K fragments: kf[0][ks]=K_hi, kf[1][ks]=K_lo (resident all sTiles)
    uint32_t kf[2][4][4];
#pragma unroll
    for (int ks = 0; ks < 4; ks++) {
        LDSM_X4(kf[0][ks][0], kf[0][ks][1], kf[0][ks][2], kf[0][ks][3],
                sKa + (aRow + ks * 16) * 2);
        LDSM_X4(kf[1][ks][0], kf[1][ks][1], kf[1][ks][2], kf[1][ks][3],
                sKa + (aRow + 64 + ks * 16) * 2);
    }

    float oacc[8][4];
#pragma unroll
    for (int nt = 0; nt < 8; nt++)
#pragma unroll
        for (int r = 0; r < 4; r++) oacc[nt][r] = 0.f;
    float m0 = -1e30f, m1 = -1e30f, l0 = 0.f, l1 = 0.f;

    for (int sTile = 0; sTile <= tTile; sTile++) {
        const int s0 = sTile * 128;
        const bool diag = (sTile == tTile);
        const int blkMax = diag ? wid : 7;   // blocks beyond this are fully masked / zero-P
        __syncthreads();
        // Q: [s][64hi|64lo]
        for (int i = tid; i < 2048; i += 256) {
            int row = i >> 4, q4 = (i & 15) * 4;
            float4 v = *(const float4*)(Qb + (size_t)(s0 + row) * N3D + q4);
            __nv_bfloat16 h0 = __float2bfloat16(v.x), h1 = __float2bfloat16(v.y);
            __nv_bfloat16 h2 = __float2bfloat16(v.z), h3 = __float2bfloat16(v.w);
            *(uint32_t*)&sQ[row * KQST + q4]     = pk2(v.x, v.y);
            *(uint32_t*)&sQ[row * KQST + q4 + 2] = pk2(v.z, v.w);
            *(uint32_t*)&sQ[row * KQST + 64 + q4] =
                pk2(v.x - __bfloat162float(h0), v.y - __bfloat162float(h1));
            *(uint32_t*)&sQ[row * KQST + 64 + q4 + 2] =
                pk2(v.z - __bfloat162float(h2), v.w - __bfloat162float(h3));
        }
        // V transposed: [e][s hi | s lo]
        for (int i = tid; i < 2048; i += 256) {
            int s = i >> 4, e4 = (i & 15) * 4;
            float4 v = *(const float4*)(Vb + (size_t)(s0 + s) * N3D + e4);
            float vv[4] = {v.x, v.y, v.z, v.w};
#pragma unroll
            for (int j = 0; j < 4; j++) {
                __nv_bfloat16 hh = __float2bfloat16(vv[j]);
                sVt[(e4 + j) * VTST + s] = hh;
                sVt[(e4 + j) * VTST + 128 + s] =
                    __float2bfloat16(vv[j] - __bfloat162float(hh));
            }
        }
        __syncthreads();

        // ---- S = K·Q^T: fused passes (Khi+Klo)·Qhi, then Khi·Qlo ----
        float sacc[16][4];
#pragma unroll
        for (int nt = 0; nt < 16; nt++)
#pragma unroll
            for (int r = 0; r < 4; r++) sacc[nt][r] = 0.f;

#pragma unroll
        for (int ks = 0; ks < 4; ks++) {
#pragma unroll
            for (int np = 0; np < 8; np++) {
                if (np > blkMax) break;
                uint32_t b0, b1, b2, b3;
                LDSM_X4(b0, b1, b2, b3,
                        sQa + (bRowQ + (uint32_t)np * 16 * KQST + ks * 16) * 2);
                mma16816(sacc[2 * np],     kf[0][ks][0], kf[0][ks][1], kf[0][ks][2], kf[0][ks][3], b0, b1);
                mma16816(sacc[2 * np + 1], kf[0][ks][0], kf[0][ks][1], kf[0][ks][2], kf[0][ks][3], b2, b3);
                mma16816(sacc[2 * np],     kf[1][ks][0], kf[1][ks][1], kf[1][ks][2], kf[1][ks][3], b0, b1);
                mma16816(sacc[2 * np + 1], kf[1][ks][0], kf[1][ks][1], kf[1][ks][2], kf[1][ks][3], b2, b3);
            }
        }
#pragma unroll
        for (int ks = 0; ks < 4; ks++) {
#pragma unroll
            for (int np = 0; np < 8; np++) {
                if (np > blkMax) break;
                uint32_t b0, b1, b2, b3;
                LDSM_X4(b0, b1, b2, b3,
                        sQa + (bRowQ + (uint32_t)np * 16 * KQST + 64 + ks * 16) * 2);
                mma16816(sacc[2 * np],     kf[0][ks][0], kf[0][ks][1], kf[0][ks][2], kf[0][ks][3], b0, b1);
                mma16816(sacc[2 * np + 1], kf[0][ks][0], kf[0][ks][1], kf[0][ks][2], kf[0][ks][3], b2, b3);
            }
        }

        // causal mask (diagonal tile only)
        if (diag) {
            const int r0l = wid * 16 + (lane >> 2);
#pragma unroll
            for (int nt = 0; nt < 16; nt++) {
                const int c = nt * 8 + (lane & 3) * 2;
                if (c > r0l)         sacc[nt][0] = -1e30f;
                if (c + 1 > r0l)     sacc[nt][1] = -1e30f;
                if (c > r0l + 8)     sacc[nt][2] = -1e30f;
                if (c + 1 > r0l + 8) sacc[nt][3] = -1e30f;
            }
        }

        // ---- online softmax + register repack to P_hi/P_lo A-fragments ----
        float rm0 = -1e30f, rm1 = -1e30f;
#pragma unroll
        for (int nt = 0; nt < 16; nt++) {
            rm0 = fmaxf(rm0, fmaxf(sacc[nt][0], sacc[nt][1]));
            rm1 = fmaxf(rm1, fmaxf(sacc[nt][2], sacc[nt][3]));
        }
        rm0 = fmaxf(rm0, __shfl_xor_sync(0xffffffffu, rm0, 1));
        rm0 = fmaxf(rm0, __shfl_xor_sync(0xffffffffu, rm0, 2));
        rm1 = fmaxf(rm1, __shfl_xor_sync(0xffffffffu, rm1, 1));
        rm1 = fmaxf(rm1, __shfl_xor_sync(0xffffffffu, rm1, 2));
        const float mn0 = fmaxf(m0, rm0), mn1 = fmaxf(m1, rm1);
        const float sc0 = __expf(m0 - mn0), sc1 = __expf(m1 - mn1);

        uint32_t phi[8][4], plo[8][4];
        float ls0 = 0.f, ls1 = 0.f;
#pragma unroll
        for (int nt = 0; nt < 16; nt++) {
            float p0 = __expf(sacc[nt][0] - mn0);
            float p1 = __expf(sacc[nt][1] - mn0);
            float p2 = __expf(sacc[nt][2] - mn1);
            float p3 = __expf(sacc[nt][3] - mn1);
            ls0 += p0 + p1; ls1 += p2 + p3;
            __nv_bfloat16 h0 = __float2bfloat16(p0), h1 = __float2bfloat16(p1);
            __nv_bfloat16 h2 = __float2bfloat16(p2), h3 = __float2bfloat16(p3);
            const int j = nt >> 1, sl = (nt & 1) * 2;
            phi[j][sl]     = pk2(p0, p1);
            phi[j][sl + 1] = pk2(p2, p3);
            plo[j][sl]     = pk2(p0 - __bfloat162float(h0), p1 - __bfloat162float(h1));
            plo[j][sl + 1] = pk2(p2 - __bfloat162float(h2), p3 - __bfloat162float(h3));
        }
        ls0 += __shfl_xor_sync(0xffffffffu, ls0, 1);
        ls0 += __shfl_xor_sync(0xffffffffu, ls0, 2);
        ls1 += __shfl_xor_sync(0xffffffffu, ls1, 1);
        ls1 += __shfl_xor_sync(0xffffffffu, ls1, 2);
        l0 = l0 * sc0 + ls0;
        l1 = l1 * sc1 + ls1;
        m0 = mn0; m1 = mn1;
#pragma unroll
        for (int nt = 0; nt < 8; nt++) {
            oacc[nt][0] *= sc0; oacc[nt][1] *= sc0;
            oacc[nt][2] *= sc1; oacc[nt][3] *= sc1;
        }

        // ---- O += P·V: fused (Phi+Plo)·Vhi, then Phi·Vlo; skip zero-P blocks ----
#pragma unroll
        for (int j = 0; j < 8; j++) {
            if (j > blkMax) break;
#pragma unroll
            for (int np = 0; np < 4; np++) {
                uint32_t b0, b1, b2, b3;
                LDSM_X4(b0, b1, b2, b3,
                        sVa + (bRowV + (uint32_t)np * 16 * VTST + (uint32_t)j * 16) * 2);
                mma16816(oacc[2 * np],     phi[j][0], phi[j][1], phi[j][2], phi[j][3], b0, b1);
                mma16816(oacc[2 * np + 1], phi[j][0], phi[j][1], phi[j][2], phi[j][3], b2, b3);
                mma16816(oacc[2 * np],     plo[j][0], plo[j][1], plo[j][2], plo[j][3], b0, b1);
                mma16816(oacc[2 * np + 1], plo[j][0], plo[j][1], plo[j][2], plo[j][3], b2, b3);
            }
        }
#pragma unroll
        for (int j = 0; j < 8; j++) {
            if (j > blkMax) break;
#pragma unroll
            for (int np = 0; np < 4; np++) {
                uint32_t b0, b1, b2, b3;
                LDSM_X4(b0, b1, b2, b3,
                        sVa + (bRowV + (uint32_t)np * 16 * VTST + 128 + (uint32_t)j * 16) * 2);
                mma16816(oacc[2 * np],     phi[j][0], phi[j][1], phi[j][2], phi[j][3], b0, b1);
                mma16816(oacc[2 * np + 1], phi[j][0], phi[j][1], phi[j][2], phi[j][3], b2, b3);
            }
        }
    }

    // epilogue: normalize, split to concat layout [m][hi|lo|hi]
    const float inv0 = 1.f / l0, inv1 = 1.f / l1;
    const int trow = t0 + wid * 16 + (lane >> 2);
    const size_t r0 = ((size_t)b * NT + trow) * KCAT;
    const size_t r1 = r0 + (size_t)8 * KCAT;
#pragma unroll
    for (int nt = 0; nt < 8; nt++) {
        const int col = h * NHD + nt * 8 + (lane & 3) * 2;
        float v0 = oacc[nt][0] * inv0, v1 = oacc[nt][1] * inv0;
        float v2 = oacc[nt][2] * inv1, v3 = oacc[nt][3] * inv1;
        __nv_bfloat16 h0 = __float2bfloat16(v0), h1 = __float2bfloat16(v1);
        __nv_bfloat16 h2 = __float2bfloat16(v2), h3 = __float2bfloat16(v3);
        uint32_t hi01 = pk2(v0, v1), hi23 = pk2(v2, v3);
        uint32_t lo01 = pk2(v0 - __bfloat162float(h0), v1 - __bfloat162float(h1));
        uint32_t lo23 = pk2(v2 - __bfloat162float(h2), v3 - __bfloat162float(h3));
        *(uint32_t*)&Ocat[r0 + col]        = hi01;
        *(uint32_t*)&Ocat[r0 + 1024 + col] = lo01;
        *(uint32_t*)&Ocat[r0 + 2048 + col] = hi01;
        *(uint32_t*)&Ocat[r1 + col]        = hi23;
        *(uint32_t*)&Ocat[r1 + 1024 + col] = lo23;
        *(uint32_t*)&Ocat[r1 + 2048 + col] = hi23;
    }
}

// ---------------- launch ----------------
extern "C" void kernel_launch(void* const* d_in, const int* in_sizes, int n_in,
                              void* d_out, int out_size) {
    const float* x  = (const float*)d_in[0];
    const float* Wi = (const float*)d_in[1];
    const float* bi = (const float*)d_in[2];
    const float* Wk = (const float*)d_in[3];
    const float* bk = (const float*)d_in[4];
    const float* Wq = (const float*)d_in[5];
    const float* bq = (const float*)d_in[6];
    const float* Wv = (const float*)d_in[7];
    const float* bv = (const float*)d_in[8];
    const float* Wo = (const float*)d_in[9];
    const float* bo = (const float*)d_in[10];
    float* out = (float*)d_out;

    float *pkqv, *pbp;
    __nv_bfloat16 *pacat, *phcat, *pb1, *pb2, *pb3;
    cudaGetSymbolAddress((void**)&pkqv,  g_kqv);
    cudaGetSymbolAddress((void**)&pbp,   g_bpack);
    cudaGetSymbolAddress((void**)&pacat, g_acat);
    cudaGetSymbolAddress((void**)&phcat, g_hcat);
    cudaGetSymbolAddress((void**)&pb1,   g_b1cat);
    cudaGetSymbolAddress((void**)&pb2,   g_b2cat);
    cudaGetSymbolAddress((void**)&pb3,   g_b3cat);

    cudaFuncSetAttribute(attn_mma, cudaFuncAttributeMaxDynamicSharedMemorySize, ATTN_SMEM);
    cudaFuncSetAttribute(gemm_mma<KCAT, 1>, cudaFuncAttributeMaxDynamicSharedMemorySize, GEMM_SMEM);
    cudaFuncSetAttribute(gemm_mma<N3D, 0>,  cudaFuncAttributeMaxDynamicSharedMemorySize, GEMM_SMEM);
    cudaFuncSetAttribute(gemm_mma<ND, 0>,   cudaFuncAttributeMaxDynamicSharedMemorySize, GEMM_SMEM);

    // weight conversions
    convW_pack<<<(N3D * 128) / 256, 256>>>(Wk, Wq, Wv, bk, bq, bv, pb2, pbp);
    convW_KN<<<(ND * 128) / 256, 256>>>(Wi, pb1);
    convW_KN<<<(ND * 128) / 256, 256>>>(Wo, pb3);

    // x -> concat
    convA_k<<<(NM * 128) / 256, 256>>>(x, pacat);

    // 1) h = x @ Wi + bi  (writes h directly in split-concat form)
    gemm_mma<KCAT, 1><<<dim3(ND / 128, NM / 128), 128, GEMM_SMEM>>>(pacat, pb1, bi, phcat);

    // 2) [K|Q|V] = h @ Wkqv + b  (f32)
    gemm_mma<N3D, 0><<<dim3(N3D / 128, NM / 128), 128, GEMM_SMEM>>>(phcat, pb2, pbp, pkqv);

    // 3) fused causal flash attention (writes attn out in split-concat form)
    attn_mma<<<dim3(NT / 128, NH, NB), 256, ATTN_SMEM>>>(pkqv, pacat);

    // 4) out = attn @ Wo + bo
    gemm_mma<ND, 0><<<dim3(ND / 128, NM / 128), 128, GEMM_SMEM>>>(pacat, pb3, bo, out);
}

// round 14
// speedup vs baseline: 2.3040x; 1.0554x over previous
#include <cuda_runtime.h>
#include <cuda_bf16.h>
#include <cuda_fp16.h>
#include <cstdint>

// Problem dims
#define NB  32
#define NT  512
#define ND  1024
#define NH  16
#define NHD 64
#define NM  (NB * NT)   // 16384 rows
#define N3D 3072
#define KCAT 3072       // tripled K for split-bf16 (hi|lo|hi) x (hi|hi|lo)
#define KC2  2048       // doubled K for split-fp16 (hi|lo) x (r|r)  [GEMM3 only]
#define BK   32

// ---------------- scratch (allocation-free: __device__ globals) ----------------
__device__ float g_kqv[(size_t)NM * N3D];                   // 192 MB
__device__ __nv_bfloat16 g_acat[(size_t)NM * KCAT];         // 96 MB  x-concat; later attn fp16 2-term
__device__ __nv_bfloat16 g_hcat[(size_t)NM * KCAT];         // 96 MB  h-concat
__device__ __nv_bfloat16 g_b1cat[(size_t)ND * KCAT];        // 6 MB   Wi^T concat
__device__ __nv_bfloat16 g_b2cat[(size_t)N3D * KCAT];       // 18 MB  Wkqv^T concat
__device__ __nv_bfloat16 g_b3cat[(size_t)ND * KCAT];        // 6 MB   Wo^T (fp16 dup uses 4 MB)
__device__ float g_bpack[N3D];                              // packed kqv bias

// ---------------- PTX helpers (compute_103-safe) ----------------
__device__ __forceinline__ uint32_t smem_u32(const void* p) {
    uint32_t a;
    asm("{ .reg .u64 t; cvta.to.shared.u64 t, %1; cvt.u32.u64 %0, t; }" : "=r"(a) : "l"(p));
    return a;
}
__device__ __forceinline__ void cp16(uint32_t dst, const void* src) {
    asm volatile("cp.async.cg.shared.global [%0], [%1], 16;" :: "r"(dst), "l"(src) : "memory");
}
#define LDSM_X4(r0, r1, r2, r3, addr) \
    asm volatile("ldmatrix.sync.aligned.m8n8.x4.shared.b16 {%0,%1,%2,%3}, [%4];" \
                 : "=r"(r0), "=r"(r1), "=r"(r2), "=r"(r3) : "r"(addr))
__device__ __forceinline__ void mma16816(float* d, uint32_t a0, uint32_t a1, uint32_t a2,
                                         uint32_t a3, uint32_t b0, uint32_t b1) {
    asm volatile(
        "mma.sync.aligned.m16n8k16.row.col.f32.bf16.bf16.f32 "
        "{%0,%1,%2,%3}, {%4,%5,%6,%7}, {%8,%9}, {%0,%1,%2,%3};"
        : "+f"(d[0]), "+f"(d[1]), "+f"(d[2]), "+f"(d[3])
        : "r"(a0), "r"(a1), "r"(a2), "r"(a3), "r"(b0), "r"(b1));
}
__device__ __forceinline__ void mma16816h(float* d, uint32_t a0, uint32_t a1, uint32_t a2,
                                          uint32_t a3, uint32_t b0, uint32_t b1) {
    asm volatile(
        "mma.sync.aligned.m16n8k16.row.col.f32.f16.f16.f32 "
        "{%0,%1,%2,%3}, {%4,%5,%6,%7}, {%8,%9}, {%0,%1,%2,%3};"
        : "+f"(d[0]), "+f"(d[1]), "+f"(d[2]), "+f"(d[3])
        : "r"(a0), "r"(a1), "r"(a2), "r"(a3), "r"(b0), "r"(b1));
}
__device__ __forceinline__ uint32_t pk2(float a, float b) {
    __nv_bfloat162 t = __floats2bfloat162_rn(a, b);
    return *(uint32_t*)&t;
}
__device__ __forceinline__ uint32_t pk2h(float a, float b) {
    __half2 t = __floats2half2_rn(a, b);
    return *(uint32_t*)&t;
}

// ---------------- conversion kernels ----------------
// A: [M,1024] f32 -> [M,3072] bf16 (hi | lo | hi)
__global__ void convA_k(const float* __restrict__ X, __nv_bfloat16* __restrict__ O) {
    int idx = blockIdx.x * 256 + threadIdx.x;    // NM*128 threads
    int m = idx >> 7, kb = (idx & 127) * 8;
    const float* xp = X + (size_t)m * ND + kb;
    float v[8];
    *(float4*)&v[0] = *(const float4*)xp;
    *(float4*)&v[4] = *(const float4*)(xp + 4);
    __nv_bfloat16 hi[8], lo[8];
#pragma unroll
    for (int j = 0; j < 8; j++) {
        hi[j] = __float2bfloat16(v[j]);
        lo[j] = __float2bfloat16(v[j] - __bfloat162float(hi[j]));
    }
    __nv_bfloat16* r = O + (size_t)m * KCAT + kb;
    *(uint4*)(r)        = *(uint4*)hi;
    *(uint4*)(r + 1024) = *(uint4*)lo;
    *(uint4*)(r + 2048) = *(uint4*)hi;
}

// W: [K=1024, N=1024] f32 row-major -> [N,3072] bf16 (hi | hi | lo)
__global__ void convW_KN(const float* __restrict__ W, __nv_bfloat16* __restrict__ O) {
    int idx = blockIdx.x * 256 + threadIdx.x;
    int n = idx >> 7, kb = (idx & 127) * 8;
    __nv_bfloat16 hi[8], lo[8];
#pragma unroll
    for (int j = 0; j < 8; j++) {
        float v = W[(size_t)(kb + j) * ND + n];
        hi[j] = __float2bfloat16(v);
        lo[j] = __float2bfloat16(v - __bfloat162float(hi[j]));
    }
    __nv_bfloat16* r = O + (size_t)n * KCAT + kb;
    *(uint4*)(r)        = *(uint4*)hi;
    *(uint4*)(r + 1024) = *(uint4*)hi;
    *(uint4*)(r + 2048) = *(uint4*)lo;
}

// Wo: [K=1024, N=1024] f32 -> [N,2048] fp16 (r | r)  (2-term scheme, B side rounded)
__global__ void convW_KN_h(const float* __restrict__ W, __half* __restrict__ O) {
    int idx = blockIdx.x * 256 + threadIdx.x;
    int n = idx >> 7, kb = (idx & 127) * 8;
    __half r8[8];
#pragma unroll
    for (int j = 0; j < 8; j++)
        r8[j] = __float2half(W[(size_t)(kb + j) * ND + n]);
    __half* r = O + (size_t)n * KC2 + kb;
    *(uint4*)(r)        = *(uint4*)r8;
    *(uint4*)(r + 1024) = *(uint4*)r8;
}

// Wk/Wq/Wv [H,D,HD] -> [3072 n-rows, 3072] bf16 (hi|hi|lo) + packed bias
__global__ void convW_pack(const float* __restrict__ Wk, const float* __restrict__ Wq,
                           const float* __restrict__ Wv, const float* __restrict__ bk,
                           const float* __restrict__ bq, const float* __restrict__ bv,
                           __nv_bfloat16* __restrict__ O, float* __restrict__ bpack) {
    int idx = blockIdx.x * 256 + threadIdx.x;
    int n = idx >> 7, kb = (idx & 127) * 8;
    int which = n >> 10, nn = n & 1023, h = nn >> 6, e = nn & 63;
    const float* W = (which == 0) ? Wk : (which == 1) ? Wq : Wv;
    __nv_bfloat16 hi[8], lo[8];
#pragma unroll
    for (int j = 0; j < 8; j++) {
        float v = W[((size_t)h * ND + kb + j) * NHD + e];
        hi[j] = __float2bfloat16(v);
        lo[j] = __float2bfloat16(v - __bfloat162float(hi[j]));
    }
    __nv_bfloat16* r = O + (size_t)n * KCAT + kb;
    *(uint4*)(r)        = *(uint4*)hi;
    *(uint4*)(r + 1024) = *(uint4*)hi;
    *(uint4*)(r + 2048) = *(uint4*)lo;
    if (kb == 0) {
        const float* bb = (which == 0) ? bk : (which == 1) ? bq : bv;
        bpack[n] = bb[nn];
    }
}

// ---------------- HMMA 16-bit GEMM: C[M,N] = Acat[M,KC] @ Bcat^T + bias ----------------
// 128x128 CTA tile, BK=32, 128 thr = 4 warps (2m x 2n), warp tile 64x64.
// 5-stage cp.async pipeline, single barrier per k-chunk.
#define AST 40
#define TILE_B2 (128 * AST * 2)             // bytes per (A or B) tile: 10240
#define STG_B   (2 * TILE_B2)               // 20480 bytes per stage
#define NSTAGE 5
#define GEMM_SMEM (NSTAGE * STG_B)          // 102400 bytes

// KC: k-extent. CN: output stride (CONCAT=0). CONCAT=1: bf16 3-term out. HALF: fp16 mma.
template <int KC, int CN, int CONCAT, int HALF>
__global__ void __launch_bounds__(128)
gemm_mma(const __nv_bfloat16* __restrict__ A, const __nv_bfloat16* __restrict__ Bt,
         const float* __restrict__ bias, void* __restrict__ Cv) {
    const int NKIT = KC / BK;
    extern __shared__ __nv_bfloat16 sm[];
    const uint32_t sbase0 = smem_u32(sm);
    const int tid = threadIdx.x;
    const int bn = blockIdx.x, bm = blockIdx.y;
    const int lane = tid & 31, wid = tid >> 5;
    const int wm = wid & 1, wn = wid >> 1;

    const int crow = tid >> 2;
    const int ccol = (tid & 3) * 8;
    const __nv_bfloat16* Ag = A + (size_t)(bm * 128 + crow) * KC + ccol;
    const __nv_bfloat16* Bg = Bt + (size_t)(bn * 128 + crow) * KC + ccol;
    const uint32_t dOff = (uint32_t)(crow * AST + ccol) * 2;

    const uint32_t aOff = (uint32_t)((wm * 64 + (lane & 15)) * AST + (lane >> 4) * 8) * 2;
    const uint32_t bOff = (uint32_t)((wn * 64 + (lane & 7) + ((lane >> 4) << 3)) * AST +
                                     ((lane >> 3) & 1) * 8) * 2;

    float acc[4][8][4];
#pragma unroll
    for (int mt = 0; mt < 4; mt++)
#pragma unroll
        for (int nt = 0; nt < 8; nt++)
#pragma unroll
            for (int r = 0; r < 4; r++) acc[mt][nt][r] = 0.f;

#pragma unroll
    for (int s = 0; s < NSTAGE - 1; s++) {
        uint32_t da = sbase0 + (uint32_t)s * STG_B + dOff;
#pragma unroll
        for (int i = 0; i < 4; i++) {
            cp16(da + (uint32_t)i * 32 * AST * 2, Ag + (size_t)i * 32 * KC + s * BK);
            cp16(da + TILE_B2 + (uint32_t)i * 32 * AST * 2, Bg + (size_t)i * 32 * KC + s * BK);
        }
        asm volatile("cp.async.commit_group;" ::: "memory");
    }

    int rb = 0, wb = NSTAGE - 1;
    for (int kc = 0; kc < NKIT; kc++) {
        asm volatile("cp.async.wait_group 3;" ::: "memory");
        __syncthreads();

        const int pf = kc + NSTAGE - 1;
        if (pf < NKIT) {
            uint32_t da = sbase0 + (uint32_t)wb * STG_B + dOff;
#pragma unroll
            for (int i = 0; i < 4; i++) {
                cp16(da + (uint32_t)i * 32 * AST * 2, Ag + (size_t)i * 32 * KC + pf * BK);
                cp16(da + TILE_B2 + (uint32_t)i * 32 * AST * 2,
                     Bg + (size_t)i * 32 * KC + pf * BK);
            }
        }
        asm volatile("cp.async.commit_group;" ::: "memory");

        const uint32_t sa = sbase0 + (uint32_t)rb * STG_B;
        const uint32_t sb = sa + TILE_B2;
#pragma unroll
        for (int ks = 0; ks < 2; ks++) {
            uint32_t af[4][4], bf[4][4];
#pragma unroll
            for (int mt = 0; mt < 4; mt++)
                LDSM_X4(af[mt][0], af[mt][1], af[mt][2], af[mt][3],
                        sa + aOff + (uint32_t)(mt * 16 * AST + ks * 16) * 2);
#pragma unroll
            for (int np = 0; np < 4; np++)
                LDSM_X4(bf[np][0], bf[np][1], bf[np][2], bf[np][3],
                        sb + bOff + (uint32_t)(np * 16 * AST + ks * 16) * 2);
#pragma unroll
            for (int mt = 0; mt < 4; mt++)
#pragma unroll
                for (int np = 0; np < 4; np++) {
                    if (HALF) {
                        mma16816h(acc[mt][2 * np],     af[mt][0], af[mt][1], af[mt][2], af[mt][3],
                                  bf[np][0], bf[np][1]);
                        mma16816h(acc[mt][2 * np + 1], af[mt][0], af[mt][1], af[mt][2], af[mt][3],
                                  bf[np][2], bf[np][3]);
                    } else {
                        mma16816(acc[mt][2 * np],     af[mt][0], af[mt][1], af[mt][2], af[mt][3],
                                 bf[np][0], bf[np][1]);
                        mma16816(acc[mt][2 * np + 1], af[mt][0], af[mt][1], af[mt][2], af[mt][3],
                                 bf[np][2], bf[np][3]);
                    }
                }
        }
        rb = (rb + 1 == NSTAGE) ? 0 : rb + 1;
        wb = (wb + 1 == NSTAGE) ? 0 : wb + 1;
    }

    // epilogue
#pragma unroll
    for (int mt = 0; mt < 4; mt++) {
        const int row = bm * 128 + wm * 64 + mt * 16 + (lane >> 2);
#pragma unroll
        for (int nt = 0; nt < 8; nt++) {
            const int col = bn * 128 + wn * 64 + nt * 8 + (lane & 3) * 2;
            const float2 b2 = *(const float2*)(bias + col);
            float v0 = acc[mt][nt][0] + b2.x, v1 = acc[mt][nt][1] + b2.y;
            float v2 = acc[mt][nt][2] + b2.x, v3 = acc[mt][nt][3] + b2.y;
            if (CONCAT) {
                __nv_bfloat16* C = (__nv_bfloat16*)Cv;
                __nv_bfloat16 h0 = __float2bfloat16(v0), h1 = __float2bfloat16(v1);
                uint32_t hi01 = pk2(v0, v1);
                uint32_t lo01 = pk2(v0 - __bfloat162float(h0), v1 - __bfloat162float(h1));
                __nv_bfloat16 h2 = __float2bfloat16(v2), h3 = __float2bfloat16(v3);
                uint32_t hi23 = pk2(v2, v3);
                uint32_t lo23 = pk2(v2 - __bfloat162float(h2), v3 - __bfloat162float(h3));
                size_t r0 = (size_t)row * KCAT, r1 = (size_t)(row + 8) * KCAT;
                *(uint32_t*)&C[r0 + col]        = hi01;
                *(uint32_t*)&C[r0 + 1024 + col] = lo01;
                *(uint32_t*)&C[r0 + 2048 + col] = hi01;
                *(uint32_t*)&C[r1 + col]        = hi23;
                *(uint32_t*)&C[r1 + 1024 + col] = lo23;
                *(uint32_t*)&C[r1 + 2048 + col] = hi23;
            } else {
                float* C = (float*)Cv;
                *(float2*)(C + (size_t)row * CN + col) = make_float2(v0, v1);
                *(float2*)(C + (size_t)(row + 8) * CN + col) = make_float2(v2, v3);
            }
        }
    }
}

// ---------------- HMMA flash attention (k/q-swapped causal, split-bf16 3-term) ----------------
// Output epilogue now emits fp16 2-term concat [O_hi|O_lo] (stride KC2) for GEMM3.
#define KQST 136                             // [128][64hi|64lo] + pad
#define VTST 264                             // [64][128hi|128lo] + pad
#define ATTN_SMEM (2 * 128 * KQST * 2 + 64 * VTST * 2)   // 103424 B

__global__ void __launch_bounds__(256)
attn_mma(const float* __restrict__ KQV, __half* __restrict__ Ocat) {
    extern __shared__ __nv_bfloat16 smb[];
    __nv_bfloat16* sK  = smb;
    __nv_bfloat16* sQ  = sK + 128 * KQST;
    __nv_bfloat16* sVt = sQ + 128 * KQST;
    const uint32_t sKa = smem_u32(sK), sQa = smem_u32(sQ), sVa = smem_u32(sVt);

    const int tTile = blockIdx.x, h = blockIdx.y, b = blockIdx.z;
    const int tid = threadIdx.x, lane = tid & 31, wid = tid >> 5;
    const int t0 = tTile * 128;

    const float* Kb = KQV + (size_t)b * NT * N3D + h * NHD;
    const float* Qb = Kb + ND;
    const float* Vb = Kb + 2 * ND;

    // K tile resident: [128][64hi|64lo]
    for (int i = tid; i < 2048; i += 256) {
        int row = i >> 4, q4 = (i & 15) * 4;
        float4 v = *(const float4*)(Kb + (size_t)(t0 + row) * N3D + q4);
        __nv_bfloat16 h0 = __float2bfloat16(v.x), h1 = __float2bfloat16(v.y);
        __nv_bfloat16 h2 = __float2bfloat16(v.z), h3 = __float2bfloat16(v.w);
        *(uint32_t*)&sK[row * KQST + q4]     = pk2(v.x, v.y);
        *(uint32_t*)&sK[row * KQST + q4 + 2] = pk2(v.z, v.w);
        *(uint32_t*)&sK[row * KQST + 64 + q4] =
            pk2(v.x - __bfloat162float(h0), v.y - __bfloat162float(h1));
        *(uint32_t*)&sK[row * KQST + 64 + q4 + 2] =
            pk2(v.z - __bfloat162float(h2), v.w - __bfloat162float(h3));
    }
    __syncthreads();

    const uint32_t aRow = (uint32_t)(wid * 16 + (lane & 15)) * KQST + (lane >> 4) * 8;
    const uint32_t bRowQ = (uint32_t)((lane & 7) + ((lane >> 4) << 3)) * KQST +
                           ((lane >> 3) & 1) * 8;
    const uint32_t bRowV = (uint32_t)((lane & 7) + ((lane >> 4) << 3)) * VTST +
                           ((lane >> 3) & 1) * 8;

    // hoist K fragments
    uint32_t kf[2][4][4];
#pragma unroll
    for (int ks = 0; ks < 4; ks++) {
        LDSM_X4(kf[0][ks][0], kf[0][ks][1], kf[0][ks][2], kf[0][ks][3],
                sKa + (aRow + ks * 16) * 2);
        LDSM_X4(kf[1][ks][0], kf[1][ks][1], kf[1][ks][2], kf[1][ks][3],
                sKa + (aRow + 64 + ks * 16) * 2);
    }

    float oacc[8][4];
#pragma unroll
    for (int nt = 0; nt < 8; nt++)
#pragma unroll
        for (int r = 0; r < 4; r++) oacc[nt][r] = 0.f;
    float m0 = -1e30f, m1 = -1e30f, l0 = 0.f, l1 = 0.f;

    for (int sTile = 0; sTile <= tTile; sTile++) {
        const int s0 = sTile * 128;
        const bool diag = (sTile == tTile);
        const int blkMax = diag ? wid : 7;
        __syncthreads();
        for (int i = tid; i < 2048; i += 256) {
            int row = i >> 4, q4 = (i & 15) * 4;
            float4 v = *(const float4*)(Qb + (size_t)(s0 + row) * N3D + q4);
            __nv_bfloat16 h0 = __float2bfloat16(v.x), h1 = __float2bfloat16(v.y);
            __nv_bfloat16 h2 = __float2bfloat16(v.z), h3 = __float2bfloat16(v.w);
            *(uint32_t*)&sQ[row * KQST + q4]     = pk2(v.x, v.y);
            *(uint32_t*)&sQ[row * KQST + q4 + 2] = pk2(v.z, v.w);
            *(uint32_t*)&sQ[row * KQST + 64 + q4] =
                pk2(v.x - __bfloat162float(h0), v.y - __bfloat162float(h1));
            *(uint32_t*)&sQ[row * KQST + 64 + q4 + 2] =
                pk2(v.z - __bfloat162float(h2), v.w - __bfloat162float(h3));
        }
        for (int i = tid; i < 2048; i += 256) {
            int s = i >> 4, e4 = (i & 15) * 4;
            float4 v = *(const float4*)(Vb + (size_t)(s0 + s) * N3D + e4);
            float vv[4] = {v.x, v.y, v.z, v.w};
#pragma unroll
            for (int j = 0; j < 4; j++) {
                __nv_bfloat16 hh = __float2bfloat16(vv[j]);
                sVt[(e4 + j) * VTST + s] = hh;
                sVt[(e4 + j) * VTST + 128 + s] =
                    __float2bfloat16(vv[j] - __bfloat162float(hh));
            }
        }
        __syncthreads();

        // ---- S = K·Q^T: fused (Khi+Klo)·Qhi, then Khi·Qlo ----
        float sacc[16][4];
#pragma unroll
        for (int nt = 0; nt < 16; nt++)
#pragma unroll
            for (int r = 0; r < 4; r++) sacc[nt][r] = 0.f;

#pragma unroll
        for (int ks = 0; ks < 4; ks++) {
#pragma unroll
            for (int np = 0; np < 8; np++) {
                if (np > blkMax) break;
                uint32_t b0, b1, b2, b3;
                LDSM_X4(b0, b1, b2, b3,
                        sQa + (bRowQ + (uint32_t)np * 16 * KQST + ks * 16) * 2);
                mma16816(sacc[2 * np],     kf[0][ks][0], kf[0][ks][1], kf[0][ks][2], kf[0][ks][3], b0, b1);
                mma16816(sacc[2 * np + 1], kf[0][ks][0], kf[0][ks][1], kf[0][ks][2], kf[0][ks][3], b2, b3);
                mma16816(sacc[2 * np],     kf[1][ks][0], kf[1][ks][1], kf[1][ks][2], kf[1][ks][3], b0, b1);
                mma16816(sacc[2 * np + 1], kf[1][ks][0], kf[1][ks][1], kf[1][ks][2], kf[1][ks][3], b2, b3);
            }
        }
#pragma unroll
        for (int ks = 0; ks < 4; ks++) {
#pragma unroll
            for (int np = 0; np < 8; np++) {
                if (np > blkMax) break;
                uint32_t b0, b1, b2, b3;
                LDSM_X4(b0, b1, b2, b3,
                        sQa + (bRowQ + (uint32_t)np * 16 * KQST + 64 + ks * 16) * 2);
                mma16816(sacc[2 * np],     kf[0][ks][0], kf[0][ks][1], kf[0][ks][2], kf[0][ks][3], b0, b1);
                mma16816(sacc[2 * np + 1], kf[0][ks][0], kf[0][ks][1], kf[0][ks][2], kf[0][ks][3], b2, b3);
            }
        }

        if (diag) {
            const int r0l = wid * 16 + (lane >> 2);
#pragma unroll
            for (int nt = 0; nt < 16; nt++) {
                const int c = nt * 8 + (lane & 3) * 2;
                if (c > r0l)         sacc[nt][0] = -1e30f;
                if (c + 1 > r0l)     sacc[nt][1] = -1e30f;
                if (c > r0l + 8)     sacc[nt][2] = -1e30f;
                if (c + 1 > r0l + 8) sacc[nt][3] = -1e30f;
            }
        }

        // ---- online softmax + P repack ----
        float rm0 = -1e30f, rm1 = -1e30f;
#pragma unroll
        for (int nt = 0; nt < 16; nt++) {
            rm0 = fmaxf(rm0, fmaxf(sacc[nt][0], sacc[nt][1]));
            rm1 = fmaxf(rm1, fmaxf(sacc[nt][2], sacc[nt][3]));
        }
        rm0 = fmaxf(rm0, __shfl_xor_sync(0xffffffffu, rm0, 1));
        rm0 = fmaxf(rm0, __shfl_xor_sync(0xffffffffu, rm0, 2));
        rm1 = fmaxf(rm1, __shfl_xor_sync(0xffffffffu, rm1, 1));
        rm1 = fmaxf(rm1, __shfl_xor_sync(0xffffffffu, rm1, 2));
        const float mn0 = fmaxf(m0, rm0), mn1 = fmaxf(m1, rm1);
        const float sc0 = __expf(m0 - mn0), sc1 = __expf(m1 - mn1);

        uint32_t phi[8][4], plo[8][4];
        float ls0 = 0.f, ls1 = 0.f;
#pragma unroll
        for (int nt = 0; nt < 16; nt++) {
            float p0 = __expf(sacc[nt][0] - mn0);
            float p1 = __expf(sacc[nt][1] - mn0);
            float p2 = __expf(sacc[nt][2] - mn1);
            float p3 = __expf(sacc[nt][3] - mn1);
            ls0 += p0 + p1; ls1 += p2 + p3;
            __nv_bfloat16 h0 = __float2bfloat16(p0), h1 = __float2bfloat16(p1);
            __nv_bfloat16 h2 = __float2bfloat16(p2), h3 = __float2bfloat16(p3);
            const int j = nt >> 1, sl = (nt & 1) * 2;
            phi[j][sl]     = pk2(p0, p1);
            phi[j][sl + 1] = pk2(p2, p3);
            plo[j][sl]     = pk2(p0 - __bfloat162float(h0), p1 - __bfloat162float(h1));
            plo[j][sl + 1] = pk2(p2 - __bfloat162float(h2), p3 - __bfloat162float(h3));
        }
        ls0 += __shfl_xor_sync(0xffffffffu, ls0, 1);
        ls0 += __shfl_xor_sync(0xffffffffu, ls0, 2);
        ls1 += __shfl_xor_sync(0xffffffffu, ls1, 1);
        ls1 += __shfl_xor_sync(0xffffffffu, ls1, 2);
        l0 = l0 * sc0 + ls0;
        l1 = l1 * sc1 + ls1;
        m0 = mn0; m1 = mn1;
#pragma unroll
        for (int nt = 0; nt < 8; nt++) {
            oacc[nt][0] *= sc0; oacc[nt][1] *= sc0;
            oacc[nt][2] *= sc1; oacc[nt][3] *= sc1;
        }

        // ---- O += P·V: fused (Phi+Plo)·Vhi, then Phi·Vlo ----
#pragma unroll
        for (int j = 0; j < 8; j++) {
            if (j > blkMax) break;
#pragma unroll
            for (int np = 0; np < 4; np++) {
                uint32_t b0, b1, b2, b3;
                LDSM_X4(b0, b1, b2, b3,
                        sVa + (bRowV + (uint32_t)np * 16 * VTST + (uint32_t)j * 16) * 2);
                mma16816(oacc[2 * np],     phi[j][0], phi[j][1], phi[j][2], phi[j][3], b0, b1);
                mma16816(oacc[2 * np + 1], phi[j][0], phi[j][1], phi[j][2], phi[j][3], b2, b3);
                mma16816(oacc[2 * np],     plo[j][0], plo[j][1], plo[j][2], plo[j][3], b0, b1);
                mma16816(oacc[2 * np + 1], plo[j][0], plo[j][1], plo[j][2], plo[j][3], b2, b3);
            }
        }
#pragma unroll
        for (int j = 0; j < 8; j++) {
            if (j > blkMax) break;
#pragma unroll
            for (int np = 0; np < 4; np++) {
                uint32_t b0, b1, b2, b3;
                LDSM_X4(b0, b1, b2, b3,
                        sVa + (bRowV + (uint32_t)np * 16 * VTST + 128 + (uint32_t)j * 16) * 2);
                mma16816(oacc[2 * np],     phi[j][0], phi[j][1], phi[j][2], phi[j][3], b0, b1);
                mma16816(oacc[2 * np + 1], phi[j][0], phi[j][1], phi[j][2], phi[j][3], b2, b3);
            }
        }
    }

    // epilogue: normalize, emit fp16 2-term concat [hi|lo] at stride KC2
    const float inv0 = 1.f / l0, inv1 = 1.f / l1;
    const int trow = t0 + wid * 16 + (lane >> 2);
    const size_t r0 = ((size_t)b * NT + trow) * KC2;
    const size_t r1 = r0 + (size_t)8 * KC2;
#pragma unroll
    for (int nt = 0; nt < 8; nt++) {
        const int col = h * NHD + nt * 8 + (lane & 3) * 2;
        float v0 = oacc[nt][0] * inv0, v1 = oacc[nt][1] * inv0;
        float v2 = oacc[nt][2] * inv1, v3 = oacc[nt][3] * inv1;
        __half h0 = __float2half(v0), h1 = __float2half(v1);
        __half h2 = __float2half(v2), h3 = __float2half(v3);
        uint32_t hi01 = pk2h(v0, v1), hi23 = pk2h(v2, v3);
        uint32_t lo01 = pk2h(v0 - __half2float(h0), v1 - __half2float(h1));
        uint32_t lo23 = pk2h(v2 - __half2float(h2), v3 - __half2float(h3));
        *(uint32_t*)&Ocat[r0 + col]        = hi01;
        *(uint32_t*)&Ocat[r0 + 1024 + col] = lo01;
        *(uint32_t*)&Ocat[r1 + col]        = hi23;
        *(uint32_t*)&Ocat[r1 + 1024 + col] = lo23;
    }
}

// ---------------- launch ----------------
extern "C" void kernel_launch(void* const* d_in, const int* in_sizes, int n_in,
                              void* d_out, int out_size) {
    const float* x  = (const float*)d_in[0];
    const float* Wi = (const float*)d_in[1];
    const float* bi = (const float*)d_in[2];
    const float* Wk = (const float*)d_in[3];
    const float* bk = (const float*)d_in[4];
    const float* Wq = (const float*)d_in[5];
    const float* bq = (const float*)d_in[6];
    const float* Wv = (const float*)d_in[7];
    const float* bv = (const float*)d_in[8];
    const float* Wo = (const float*)d_in[9];
    const float* bo = (const float*)d_in[10];
    float* out = (float*)d_out;

    float *pkqv, *pbp;
    __nv_bfloat16 *pacat, *phcat, *pb1, *pb2, *pb3;
    cudaGetSymbolAddress((void**)&pkqv,  g_kqv);
    cudaGetSymbolAddress((void**)&pbp,   g_bpack);
    cudaGetSymbolAddress((void**)&pacat, g_acat);
    cudaGetSymbolAddress((void**)&phcat, g_hcat);
    cudaGetSymbolAddress((void**)&pb1,   g_b1cat);
    cudaGetSymbolAddress((void**)&pb2,   g_b2cat);
    cudaGetSymbolAddress((void**)&pb3,   g_b3cat);

    cudaFuncSetAttribute(attn_mma, cudaFuncAttributeMaxDynamicSharedMemorySize, ATTN_SMEM);
    cudaFuncSetAttribute(gemm_mma<KCAT, KCAT, 1, 0>, cudaFuncAttributeMaxDynamicSharedMemorySize, GEMM_SMEM);
    cudaFuncSetAttribute(gemm_mma<KCAT, N3D, 0, 0>,  cudaFuncAttributeMaxDynamicSharedMemorySize, GEMM_SMEM);
    cudaFuncSetAttribute(gemm_mma<KC2, ND, 0, 1>,    cudaFuncAttributeMaxDynamicSharedMemorySize, GEMM_SMEM);

    // Launch order chosen so the 4th launch (the one ncu captures) is gemm_mma.
    // 1) weight pack for kqv
    convW_pack<<<(N3D * 128) / 256, 256>>>(Wk, Wq, Wv, bk, bq, bv, pb2, pbp);
    // 2) x -> concat
    convA_k<<<(NM * 128) / 256, 256>>>(x, pacat);
    // 3) Wi concat
    convW_KN<<<(ND * 128) / 256, 256>>>(Wi, pb1);
    // 4) h = x @ Wi + bi  (PROFILED)
    gemm_mma<KCAT, KCAT, 1, 0><<<dim3(ND / 128, NM / 128), 128, GEMM_SMEM>>>(pacat, pb1, bi, phcat);
    // 5) Wo fp16 dup
    convW_KN_h<<<(ND * 128) / 256, 256>>>(Wo, (__half*)pb3);
    // 6) [K|Q|V] = h @ Wkqv + b
    gemm_mma<KCAT, N3D, 0, 0><<<dim3(N3D / 128, NM / 128), 128, GEMM_SMEM>>>(phcat, pb2, pbp, pkqv);
    // 7) fused causal flash attention (emits fp16 2-term concat)
    attn_mma<<<dim3(NT / 128, NH, NB), 256, ATTN_SMEM>>>(pkqv, (__half*)pacat);
    // 8) out = attn @ Wo + bo  (fp16 2-term)
    gemm_mma<KC2, ND, 0, 1><<<dim3(ND / 128, NM / 128), 128, GEMM_SMEM>>>(pacat, pb3, bo, out);
}